// round 3
// baseline (speedup 1.0000x reference)
#include <cuda_runtime.h>
#include <math.h>
#include <stdint.h>

#define Bb 8
#define Ss 2048
#define Dd 768
#define Hh 8
#define HD 96
#define M_ROWS (Bb*Ss)          // 16384
#define SW (Ss/32)              // mask words per row = 64

// ---------------- scratch (static device globals; no allocs) ----------------
__device__ float    g_Q[(size_t)Bb*Hh*Ss*HD];
__device__ float    g_K[(size_t)Bb*Hh*Ss*HD];
__device__ float    g_V[(size_t)Bb*Hh*Ss*HD];
__device__ float    g_CTX[(size_t)Bb*Ss*Dd];
__device__ uint32_t g_mask[(size_t)Bb*Ss*SW];

// ---------------- 1) pack adj (int32 0/1) into bitmask ----------------
__global__ void pack_mask_kernel(const int* __restrict__ adj) {
    size_t idx = (size_t)blockIdx.x * blockDim.x + threadIdx.x;  // one per adj element
    int v = adj[idx];
    unsigned bits = __ballot_sync(0xffffffffu, v != 0);
    if ((threadIdx.x & 31) == 0) g_mask[idx >> 5] = bits;
}

// ---------------- 2) projection GEMM: out = X @ W^T + b, scattered to [B,H,S,HD] ----------------
#define BM 64
#define BN 64
#define BK 16

__global__ __launch_bounds__(256) void proj_kernel(
    const float* __restrict__ X,   // [M_ROWS, D]
    const float* __restrict__ W,   // [D, D] row-major; y[m,n] = sum_k X[m,k]*W[n,k]
    const float* __restrict__ bias,
    float* __restrict__ out)       // [B,H,S,HD]
{
    __shared__ float As[BM][BK + 1];
    __shared__ float Bs[BN][BK + 1];

    const int tid = threadIdx.x;
    const int tr = tid >> 4;       // 0..15
    const int tc = tid & 15;       // 0..15
    const int rowBase = blockIdx.y * BM;
    const int colBase = blockIdx.x * BN;

    float acc[4][4];
#pragma unroll
    for (int i = 0; i < 4; i++)
#pragma unroll
        for (int j = 0; j < 4; j++) acc[i][j] = 0.f;

    for (int k0 = 0; k0 < Dd; k0 += BK) {
#pragma unroll
        for (int i = tid; i < BM * BK; i += 256) {
            int r = i / BK, c = i % BK;
            As[r][c] = X[(size_t)(rowBase + r) * Dd + k0 + c];
        }
#pragma unroll
        for (int i = tid; i < BN * BK; i += 256) {
            int r = i / BK, c = i % BK;
            Bs[r][c] = W[(size_t)(colBase + r) * Dd + k0 + c];
        }
        __syncthreads();
#pragma unroll
        for (int kk = 0; kk < BK; kk++) {
            float a[4], b[4];
#pragma unroll
            for (int i = 0; i < 4; i++) a[i] = As[tr * 4 + i][kk];
#pragma unroll
            for (int j = 0; j < 4; j++) b[j] = Bs[tc * 4 + j][kk];
#pragma unroll
            for (int i = 0; i < 4; i++)
#pragma unroll
                for (int j = 0; j < 4; j++) acc[i][j] = fmaf(a[i], b[j], acc[i][j]);
        }
        __syncthreads();
    }

#pragma unroll
    for (int i = 0; i < 4; i++) {
        int m = rowBase + tr * 4 + i;
        int b_ = m / Ss, s_ = m % Ss;
#pragma unroll
        for (int j = 0; j < 4; j++) {
            int n = colBase + tc * 4 + j;
            int h_ = n / HD, hd_ = n % HD;
            out[(((size_t)b_ * Hh + h_) * Ss + s_) * HD + hd_] = acc[i][j] + bias[n];
        }
    }
}

// ---------------- 3) flash attention with bitmask + fused residual ----------------
#define BQ 64
#define BKV 64
#define LDQ 97      // padded row stride for Q/K/V tiles
#define LDS 65      // padded row stride for score tile
#define NKT (Ss / BKV)   // 32

// dynamic smem layout (floats):
//  Qs[BQ*LDQ] | Ks[BKV*LDQ] | Vs[BKV*LDQ] | Ssm[BQ*LDS] | m[BQ] | l[BQ] | alpha[BQ] | Ms[BQ*2] (u32)
#define ATTN_SMEM_FLOATS (3 * BQ * LDQ + BQ * LDS + 3 * BQ + 2 * BQ)
#define ATTN_SMEM_BYTES  (ATTN_SMEM_FLOATS * 4)

__global__ __launch_bounds__(256) void attn_kernel(const float* __restrict__ feat)
{
    extern __shared__ float smem[];
    float* Qs      = smem;
    float* Ks      = Qs + BQ * LDQ;
    float* Vs      = Ks + BKV * LDQ;
    float* Ssm     = Vs + BKV * LDQ;
    float* m_s     = Ssm + BQ * LDS;
    float* l_s     = m_s + BQ;
    float* alpha_s = l_s + BQ;
    uint32_t* Ms   = (uint32_t*)(alpha_s + BQ);

    const int tid = threadIdx.x;
    const int qt = blockIdx.x, h = blockIdx.y, b = blockIdx.z;
    const int tr = tid >> 4;   // 0..15 -> rows tr*4..+3
    const int tc = tid & 15;   // 0..15

    const float* Qg = g_Q + (((size_t)b * Hh + h) * Ss + (size_t)qt * BQ) * HD;
    const float* Kg = g_K + ((size_t)b * Hh + h) * Ss * HD;
    const float* Vg = g_V + ((size_t)b * Hh + h) * Ss * HD;

    for (int i = tid; i < BQ * HD; i += 256)
        Qs[(i / HD) * LDQ + (i % HD)] = Qg[i];
    if (tid < BQ) { m_s[tid] = -INFINITY; l_s[tid] = 0.f; }

    float acc[4][6];
#pragma unroll
    for (int i = 0; i < 4; i++)
#pragma unroll
        for (int j = 0; j < 6; j++) acc[i][j] = 0.f;

    const float scale = 0.10206207261596577f;   // 1/sqrt(96)

    for (int kt = 0; kt < NKT; kt++) {
        __syncthreads();   // protect Ks/Vs/Ssm from previous iteration's readers
        const float* Kt = Kg + (size_t)kt * BKV * HD;
        const float* Vt = Vg + (size_t)kt * BKV * HD;
        for (int i = tid; i < BKV * HD; i += 256) {
            int r = i / HD, c = i % HD;
            Ks[r * LDQ + c] = Kt[i];
            Vs[r * LDQ + c] = Vt[i];
        }
        if (tid < BQ * 2) {
            int r = tid >> 1, w = tid & 1;
            Ms[tid] = g_mask[((size_t)b * Ss + qt * BQ + r) * SW + kt * 2 + w];
        }
        __syncthreads();

        // --- scores: S = Q @ K^T (this thread: rows tr*4..+3, cols tc*4..+3) ---
        float sc[4][4];
#pragma unroll
        for (int i = 0; i < 4; i++)
#pragma unroll
            for (int j = 0; j < 4; j++) sc[i][j] = 0.f;
#pragma unroll 4
        for (int k = 0; k < HD; k++) {
            float a[4], bb[4];
#pragma unroll
            for (int i = 0; i < 4; i++) a[i]  = Qs[(tr * 4 + i) * LDQ + k];
#pragma unroll
            for (int j = 0; j < 4; j++) bb[j] = Ks[(tc * 4 + j) * LDQ + k];
#pragma unroll
            for (int i = 0; i < 4; i++)
#pragma unroll
                for (int j = 0; j < 4; j++) sc[i][j] = fmaf(a[i], bb[j], sc[i][j]);
        }
#pragma unroll
        for (int i = 0; i < 4; i++) {
            int r = tr * 4 + i;
#pragma unroll
            for (int j = 0; j < 4; j++) {
                int c = tc * 4 + j;
                uint32_t bits = Ms[r * 2 + (c >> 5)];
                float v = ((bits >> (c & 31)) & 1u) ? sc[i][j] * scale : -1e9f;
                Ssm[r * LDS + c] = v;
            }
        }
        __syncthreads();

        // --- online softmax: 4 threads per row ---
        {
            int row = tid >> 2, sub = tid & 3;
            float pv[16];
            float tmax = -INFINITY;
#pragma unroll
            for (int t = 0; t < 16; t++) {
                pv[t] = Ssm[row * LDS + sub * 16 + t];
                tmax = fmaxf(tmax, pv[t]);
            }
            tmax = fmaxf(tmax, __shfl_xor_sync(0xffffffffu, tmax, 1));
            tmax = fmaxf(tmax, __shfl_xor_sync(0xffffffffu, tmax, 2));
            float m_old = m_s[row];
            float m_new = fmaxf(m_old, tmax);
            float suml = 0.f;
#pragma unroll
            for (int t = 0; t < 16; t++) {
                float p = __expf(pv[t] - m_new);
                Ssm[row * LDS + sub * 16 + t] = p;
                suml += p;
            }
            suml += __shfl_xor_sync(0xffffffffu, suml, 1);
            suml += __shfl_xor_sync(0xffffffffu, suml, 2);
            if (sub == 0) {
                float alpha = __expf(m_old - m_new);
                l_s[row] = l_s[row] * alpha + suml;
                m_s[row] = m_new;
                alpha_s[row] = alpha;
            }
        }
        __syncthreads();

        // --- rescale accumulator, then O += P @ V (rows tr*4..+3, cols tc*6..+5) ---
#pragma unroll
        for (int i = 0; i < 4; i++) {
            float al = alpha_s[tr * 4 + i];
#pragma unroll
            for (int j = 0; j < 6; j++) acc[i][j] *= al;
        }
#pragma unroll 4
        for (int c = 0; c < BKV; c++) {
            float p[4], v[6];
#pragma unroll
            for (int i = 0; i < 4; i++) p[i] = Ssm[(tr * 4 + i) * LDS + c];
#pragma unroll
            for (int j = 0; j < 6; j++) v[j] = Vs[c * LDQ + tc * 6 + j];
#pragma unroll
            for (int i = 0; i < 4; i++)
#pragma unroll
                for (int j = 0; j < 6; j++) acc[i][j] = fmaf(p[i], v[j], acc[i][j]);
        }
    }

    // --- epilogue: ctx = O/l + residual ---
#pragma unroll
    for (int i = 0; i < 4; i++) {
        int r = tr * 4 + i;
        int q = qt * BQ + r;
        float invl = 1.f / l_s[r];
#pragma unroll
        for (int j = 0; j < 6; j++) {
            int d = h * HD + tc * 6 + j;
            size_t idx = ((size_t)b * Ss + q) * Dd + d;
            g_CTX[idx] = acc[i][j] * invl + feat[idx];
        }
    }
}

// ---------------- 4) LayerNorm over D=768 ----------------
__global__ __launch_bounds__(256) void ln_kernel(
    const float* __restrict__ gamma, const float* __restrict__ beta,
    float* __restrict__ out)
{
    __shared__ float red[16];
    const int row = blockIdx.x;
    const int tid = threadIdx.x;
    const float* x = g_CTX + (size_t)row * Dd;

    float v[3];
    float sum = 0.f, sq = 0.f;
#pragma unroll
    for (int t = 0; t < 3; t++) {
        v[t] = x[tid + t * 256];
        sum += v[t];
        sq  = fmaf(v[t], v[t], sq);
    }
#pragma unroll
    for (int o = 16; o > 0; o >>= 1) {
        sum += __shfl_xor_sync(0xffffffffu, sum, o);
        sq  += __shfl_xor_sync(0xffffffffu, sq, o);
    }
    int warp = tid >> 5;
    if ((tid & 31) == 0) { red[warp] = sum; red[warp + 8] = sq; }
    __syncthreads();
    if (tid < 32) {
        float s = (tid < 8) ? red[tid] : 0.f;
        float q = (tid < 8) ? red[tid + 8] : 0.f;
#pragma unroll
        for (int o = 4; o > 0; o >>= 1) {
            s += __shfl_xor_sync(0xffffffffu, s, o);
            q += __shfl_xor_sync(0xffffffffu, q, o);
        }
        if (tid == 0) { red[0] = s; red[1] = q; }
    }
    __syncthreads();
    float mu = red[0] * (1.f / Dd);
    float var = red[1] * (1.f / Dd) - mu * mu;
    float rs = rsqrtf(var + 1e-5f);
#pragma unroll
    for (int t = 0; t < 3; t++) {
        int d = tid + t * 256;
        out[(size_t)row * Dd + d] = (v[t] - mu) * rs * gamma[d] + beta[d];
    }
}

// ---------------- launch ----------------
extern "C" void kernel_launch(void* const* d_in, const int* in_sizes, int n_in,
                              void* d_out, int out_size)
{
    const float* feat  = (const float*)d_in[0];
    const int*   adj   = (const int*)d_in[1];
    const float* Wq    = (const float*)d_in[2];
    const float* bq    = (const float*)d_in[3];
    const float* Wk    = (const float*)d_in[4];
    const float* bk    = (const float*)d_in[5];
    const float* Wv    = (const float*)d_in[6];
    const float* bv    = (const float*)d_in[7];
    const float* gamma = (const float*)d_in[8];
    const float* beta  = (const float*)d_in[9];
    float* out = (float*)d_out;

    float *Qp, *Kp, *Vp;
    cudaGetSymbolAddress((void**)&Qp, g_Q);
    cudaGetSymbolAddress((void**)&Kp, g_K);
    cudaGetSymbolAddress((void**)&Vp, g_V);

    // 1) pack adjacency into bitmask
    {
        size_t n = (size_t)Bb * Ss * Ss;
        pack_mask_kernel<<<(unsigned)(n / 256), 256>>>(adj);
    }

    // 2) QKV projections
    dim3 pgrid(Dd / BN, M_ROWS / BM);
    proj_kernel<<<pgrid, 256>>>(feat, Wq, bq, Qp);
    proj_kernel<<<pgrid, 256>>>(feat, Wk, bk, Kp);
    proj_kernel<<<pgrid, 256>>>(feat, Wv, bv, Vp);

    // 3) attention (needs >48KB dynamic smem)
    cudaFuncSetAttribute(attn_kernel, cudaFuncAttributeMaxDynamicSharedMemorySize,
                         ATTN_SMEM_BYTES);
    attn_kernel<<<dim3(Ss / BQ, Hh, Bb), 256, ATTN_SMEM_BYTES>>>(feat);

    // 4) layernorm
    ln_kernel<<<M_ROWS, 256>>>(gamma, beta, out);
}

// round 4
// speedup vs baseline: 1.2810x; 1.2810x over previous
#include <cuda_runtime.h>
#include <math.h>
#include <stdint.h>

#define Bb 8
#define Ss 2048
#define Dd 768
#define Hh 8
#define HD 96
#define M_ROWS (Bb*Ss)          // 16384
#define SW (Ss/32)              // mask words per row = 64

// ---------------- scratch (static device globals; no allocs) ----------------
__device__ float    g_Q[(size_t)Bb*Hh*Ss*HD];
__device__ float    g_K[(size_t)Bb*Hh*Ss*HD];
__device__ float    g_V[(size_t)Bb*Hh*Ss*HD];
__device__ float    g_CTX[(size_t)Bb*Ss*Dd];
__device__ uint32_t g_mask[(size_t)Bb*Ss*SW];

// ---------------- 1) pack adj (int32 0/1) into bitmask ----------------
__global__ void pack_mask_kernel(const int* __restrict__ adj) {
    size_t idx = (size_t)blockIdx.x * blockDim.x + threadIdx.x;
    int v = adj[idx];
    unsigned bits = __ballot_sync(0xffffffffu, v != 0);
    if ((threadIdx.x & 31) == 0) g_mask[idx >> 5] = bits;
}

// ---------------- 2) projection GEMM v2: 128x128x8, 8x8 microtile ----------------
#define PBM 128
#define PBN 128
#define PBK 8
#define PLD 132

__global__ __launch_bounds__(256, 2) void proj_kernel(
    const float* __restrict__ X,   // [M_ROWS, D]
    const float* __restrict__ W,   // [D, D]; y[m,n] = sum_k X[m,k]*W[n,k]
    const float* __restrict__ bias,
    float* __restrict__ out)       // [B,H,S,HD]
{
    __shared__ float As[2][PBK][PLD];
    __shared__ float Bs[2][PBK][PLD];

    const int tid = threadIdx.x;
    const int tr = tid >> 4;          // 0..15
    const int tc = tid & 15;          // 0..15
    const int rowBase = blockIdx.y * PBM;
    const int colBase = blockIdx.x * PBN;

    const int lm = tid >> 1;          // 0..127 (tile row for loading)
    const int lk = (tid & 1) * 4;     // 0 or 4

    const float* Xp = X + (size_t)(rowBase + lm) * Dd + lk;
    const float* Wp = W + (size_t)(colBase + lm) * Dd + lk;

    float acc[8][8];
#pragma unroll
    for (int i = 0; i < 8; i++)
#pragma unroll
        for (int j = 0; j < 8; j++) acc[i][j] = 0.f;

    // preload first tile
    float4 ra = *(const float4*)(Xp + 0);
    float4 rb = *(const float4*)(Wp + 0);
    As[0][lk + 0][lm] = ra.x; As[0][lk + 1][lm] = ra.y;
    As[0][lk + 2][lm] = ra.z; As[0][lk + 3][lm] = ra.w;
    Bs[0][lk + 0][lm] = rb.x; Bs[0][lk + 1][lm] = rb.y;
    Bs[0][lk + 2][lm] = rb.z; Bs[0][lk + 3][lm] = rb.w;
    __syncthreads();

    int buf = 0;
    for (int k0 = 0; k0 < Dd; k0 += PBK) {
        float4 na, nb;
        const bool has_next = (k0 + PBK < Dd);
        if (has_next) {
            na = *(const float4*)(Xp + k0 + PBK);
            nb = *(const float4*)(Wp + k0 + PBK);
        }
#pragma unroll
        for (int kk = 0; kk < PBK; kk++) {
            float4 a0 = *(float4*)&As[buf][kk][tr * 8];
            float4 a1 = *(float4*)&As[buf][kk][tr * 8 + 4];
            float4 b0 = *(float4*)&Bs[buf][kk][tc * 8];
            float4 b1 = *(float4*)&Bs[buf][kk][tc * 8 + 4];
            float a[8] = {a0.x, a0.y, a0.z, a0.w, a1.x, a1.y, a1.z, a1.w};
            float b[8] = {b0.x, b0.y, b0.z, b0.w, b1.x, b1.y, b1.z, b1.w};
#pragma unroll
            for (int i = 0; i < 8; i++)
#pragma unroll
                for (int j = 0; j < 8; j++) acc[i][j] = fmaf(a[i], b[j], acc[i][j]);
        }
        if (has_next) {
            int nb_ = buf ^ 1;
            As[nb_][lk + 0][lm] = na.x; As[nb_][lk + 1][lm] = na.y;
            As[nb_][lk + 2][lm] = na.z; As[nb_][lk + 3][lm] = na.w;
            Bs[nb_][lk + 0][lm] = nb.x; Bs[nb_][lk + 1][lm] = nb.y;
            Bs[nb_][lk + 2][lm] = nb.z; Bs[nb_][lk + 3][lm] = nb.w;
        }
        __syncthreads();
        buf ^= 1;
    }

    float bias8[8];
#pragma unroll
    for (int j = 0; j < 8; j++) bias8[j] = bias[colBase + tc * 8 + j];

#pragma unroll
    for (int i = 0; i < 8; i++) {
        int m = rowBase + tr * 8 + i;
        int b_ = m >> 11, s_ = m & (Ss - 1);
#pragma unroll
        for (int g = 0; g < 2; g++) {
            int n0 = colBase + tc * 8 + g * 4;
            int h_ = n0 / HD, hd = n0 - h_ * HD;   // 4-col group never crosses head (96 % 4 == 0)
            float4 o;
            o.x = acc[i][g * 4 + 0] + bias8[g * 4 + 0];
            o.y = acc[i][g * 4 + 1] + bias8[g * 4 + 1];
            o.z = acc[i][g * 4 + 2] + bias8[g * 4 + 2];
            o.w = acc[i][g * 4 + 3] + bias8[g * 4 + 3];
            *(float4*)&out[(((size_t)b_ * Hh + h_) * Ss + s_) * HD + hd] = o;
        }
    }
}

// ---------------- 3) flash attention v2: BQ=128, BKV=128, 8x8 / 8x6 microtiles ----------------
#define AQ 128
#define AKV 128
#define QLD 132     // Qs/Ks stride: [k][q], k<96
#define VLD 104     // Vs stride: [c][hd]
#define SLD 132     // Ssm stride: [r][c]
#define ANKT (Ss / AKV)   // 16

#define ATTN_F (2 * HD * QLD + AKV * VLD + AQ * SLD + 3 * AQ + AQ * 4)
#define ATTN_SMEM_BYTES (ATTN_F * 4)

__global__ __launch_bounds__(256, 1) void attn_kernel(const float* __restrict__ feat)
{
    extern __shared__ float smem[];
    float* Qs      = smem;                    // [96][132] transposed
    float* Ks      = Qs + HD * QLD;           // [96][132] transposed
    float* Vs      = Ks + HD * QLD;           // [128][104]
    float* Ssm     = Vs + AKV * VLD;          // [128][132]
    float* m_s     = Ssm + AQ * SLD;
    float* l_s     = m_s + AQ;
    float* alpha_s = l_s + AQ;
    uint32_t* Ms   = (uint32_t*)(alpha_s + AQ);  // [128][4]

    const int tid = threadIdx.x;
    const int qt = blockIdx.x, h = blockIdx.y, b = blockIdx.z;
    const int tr = tid >> 4;   // 0..15 -> rows tr*8..+7
    const int tc = tid & 15;   // 0..15

    const float* Qg = g_Q + (((size_t)b * Hh + h) * Ss + (size_t)qt * AQ) * HD;
    const float* Kg = g_K + ((size_t)b * Hh + h) * Ss * HD;
    const float* Vg = g_V + ((size_t)b * Hh + h) * Ss * HD;

    // load Q transposed: Qs[k][q]
    for (int i = tid; i < AQ * HD / 4; i += 256) {
        int q = i / 24, hd4 = (i % 24) * 4;
        float4 v = *(const float4*)&Qg[q * HD + hd4];
        Qs[(hd4 + 0) * QLD + q] = v.x;
        Qs[(hd4 + 1) * QLD + q] = v.y;
        Qs[(hd4 + 2) * QLD + q] = v.z;
        Qs[(hd4 + 3) * QLD + q] = v.w;
    }
    if (tid < AQ) { m_s[tid] = -INFINITY; l_s[tid] = 0.f; }

    float acc[8][6];
#pragma unroll
    for (int i = 0; i < 8; i++)
#pragma unroll
        for (int j = 0; j < 6; j++) acc[i][j] = 0.f;

    const float scale = 0.10206207261596577f;   // 1/sqrt(96)

    for (int kt = 0; kt < ANKT; kt++) {
        __syncthreads();   // previous iteration's readers of Ks/Vs/Ssm/Ms done
        const float* Kt = Kg + (size_t)kt * AKV * HD;
        const float* Vt = Vg + (size_t)kt * AKV * HD;
        for (int i = tid; i < AKV * HD / 4; i += 256) {
            int c = i / 24, hd4 = (i % 24) * 4;
            float4 kv = *(const float4*)&Kt[c * HD + hd4];
            Ks[(hd4 + 0) * QLD + c] = kv.x;
            Ks[(hd4 + 1) * QLD + c] = kv.y;
            Ks[(hd4 + 2) * QLD + c] = kv.z;
            Ks[(hd4 + 3) * QLD + c] = kv.w;
            float4 vv = *(const float4*)&Vt[c * HD + hd4];
            *(float4*)&Vs[c * VLD + hd4] = vv;
        }
        for (int i = tid; i < AQ * 4; i += 256)
            Ms[i] = g_mask[((size_t)b * Ss + qt * AQ + (i >> 2)) * SW + kt * 4 + (i & 3)];
        __syncthreads();

        // --- scores: S = Q @ K^T, 8x8 microtile, all-float4 LDS ---
        float sc[8][8];
#pragma unroll
        for (int i = 0; i < 8; i++)
#pragma unroll
            for (int j = 0; j < 8; j++) sc[i][j] = 0.f;
#pragma unroll 2
        for (int k = 0; k < HD; k++) {
            float4 a0 = *(float4*)&Qs[k * QLD + tr * 8];
            float4 a1 = *(float4*)&Qs[k * QLD + tr * 8 + 4];
            float4 b0 = *(float4*)&Ks[k * QLD + tc * 8];
            float4 b1 = *(float4*)&Ks[k * QLD + tc * 8 + 4];
            float a[8] = {a0.x, a0.y, a0.z, a0.w, a1.x, a1.y, a1.z, a1.w};
            float bb[8] = {b0.x, b0.y, b0.z, b0.w, b1.x, b1.y, b1.z, b1.w};
#pragma unroll
            for (int i = 0; i < 8; i++)
#pragma unroll
                for (int j = 0; j < 8; j++) sc[i][j] = fmaf(a[i], bb[j], sc[i][j]);
        }
        // mask + scale + store (two float4 stores per row)
#pragma unroll
        for (int i = 0; i < 8; i++) {
            int r = tr * 8 + i;
            uint32_t word = Ms[r * 4 + (tc >> 2)];
            int bitbase = (tc & 3) * 8;
            float4 s0, s1;
            s0.x = ((word >> (bitbase + 0)) & 1u) ? sc[i][0] * scale : -1e9f;
            s0.y = ((word >> (bitbase + 1)) & 1u) ? sc[i][1] * scale : -1e9f;
            s0.z = ((word >> (bitbase + 2)) & 1u) ? sc[i][2] * scale : -1e9f;
            s0.w = ((word >> (bitbase + 3)) & 1u) ? sc[i][3] * scale : -1e9f;
            s1.x = ((word >> (bitbase + 4)) & 1u) ? sc[i][4] * scale : -1e9f;
            s1.y = ((word >> (bitbase + 5)) & 1u) ? sc[i][5] * scale : -1e9f;
            s1.z = ((word >> (bitbase + 6)) & 1u) ? sc[i][6] * scale : -1e9f;
            s1.w = ((word >> (bitbase + 7)) & 1u) ? sc[i][7] * scale : -1e9f;
            *(float4*)&Ssm[r * SLD + tc * 8]     = s0;
            *(float4*)&Ssm[r * SLD + tc * 8 + 4] = s1;
        }
        __syncthreads();

        // --- online softmax: 2 threads per row, 64 cols each, vectorized ---
        {
            int row = tid >> 1, sub = tid & 1;
            float* Sr = Ssm + row * SLD + sub * 64;
            float tmax = -INFINITY;
#pragma unroll
            for (int t = 0; t < 16; t++) {
                float4 v = *(float4*)&Sr[t * 4];
                tmax = fmaxf(tmax, fmaxf(fmaxf(v.x, v.y), fmaxf(v.z, v.w)));
            }
            tmax = fmaxf(tmax, __shfl_xor_sync(0xffffffffu, tmax, 1));
            float m_old = m_s[row];
            float m_new = fmaxf(m_old, tmax);
            float suml = 0.f;
#pragma unroll
            for (int t = 0; t < 16; t++) {
                float4 v = *(float4*)&Sr[t * 4];
                v.x = __expf(v.x - m_new);
                v.y = __expf(v.y - m_new);
                v.z = __expf(v.z - m_new);
                v.w = __expf(v.w - m_new);
                suml += (v.x + v.y) + (v.z + v.w);
                *(float4*)&Sr[t * 4] = v;
            }
            suml += __shfl_xor_sync(0xffffffffu, suml, 1);
            if (sub == 0) {
                float alpha = __expf(m_old - m_new);
                l_s[row] = l_s[row] * alpha + suml;
                m_s[row] = m_new;
                alpha_s[row] = alpha;
            }
        }
        __syncthreads();

        // --- rescale acc, then O += P @ V (8 rows x 6 cols, P vectorized along c) ---
#pragma unroll
        for (int i = 0; i < 8; i++) {
            float al = alpha_s[tr * 8 + i];
#pragma unroll
            for (int j = 0; j < 6; j++) acc[i][j] *= al;
        }
        for (int c0 = 0; c0 < AKV; c0 += 4) {
            float pr[8][4];
#pragma unroll
            for (int i = 0; i < 8; i++) {
                float4 t = *(float4*)&Ssm[(tr * 8 + i) * SLD + c0];
                pr[i][0] = t.x; pr[i][1] = t.y; pr[i][2] = t.z; pr[i][3] = t.w;
            }
#pragma unroll
            for (int cc = 0; cc < 4; cc++) {
                const float* Vr = Vs + (c0 + cc) * VLD + tc * 6;
                float2 v0 = *(float2*)&Vr[0];
                float2 v1 = *(float2*)&Vr[2];
                float2 v2 = *(float2*)&Vr[4];
                float v[6] = {v0.x, v0.y, v1.x, v1.y, v2.x, v2.y};
#pragma unroll
                for (int i = 0; i < 8; i++) {
                    float p = pr[i][cc];
#pragma unroll
                    for (int j = 0; j < 6; j++) acc[i][j] = fmaf(p, v[j], acc[i][j]);
                }
            }
        }
    }

    // --- epilogue: ctx = O/l + residual ---
#pragma unroll
    for (int i = 0; i < 8; i++) {
        int r = tr * 8 + i;
        int q = qt * AQ + r;
        float invl = 1.f / l_s[r];
        size_t base = ((size_t)b * Ss + q) * Dd + h * HD + tc * 6;
#pragma unroll
        for (int j = 0; j < 6; j++)
            g_CTX[base + j] = acc[i][j] * invl + feat[base + j];
    }
}

// ---------------- 4) LayerNorm over D=768 ----------------
__global__ __launch_bounds__(256) void ln_kernel(
    const float* __restrict__ gamma, const float* __restrict__ beta,
    float* __restrict__ out)
{
    __shared__ float red[16];
    const int row = blockIdx.x;
    const int tid = threadIdx.x;
    const float* x = g_CTX + (size_t)row * Dd;

    float v[3];
    float sum = 0.f, sq = 0.f;
#pragma unroll
    for (int t = 0; t < 3; t++) {
        v[t] = x[tid + t * 256];
        sum += v[t];
        sq  = fmaf(v[t], v[t], sq);
    }
#pragma unroll
    for (int o = 16; o > 0; o >>= 1) {
        sum += __shfl_xor_sync(0xffffffffu, sum, o);
        sq  += __shfl_xor_sync(0xffffffffu, sq, o);
    }
    int warp = tid >> 5;
    if ((tid & 31) == 0) { red[warp] = sum; red[warp + 8] = sq; }
    __syncthreads();
    if (tid < 32) {
        float s = (tid < 8) ? red[tid] : 0.f;
        float q = (tid < 8) ? red[tid + 8] : 0.f;
#pragma unroll
        for (int o = 4; o > 0; o >>= 1) {
            s += __shfl_xor_sync(0xffffffffu, s, o);
            q += __shfl_xor_sync(0xffffffffu, q, o);
        }
        if (tid == 0) { red[0] = s; red[1] = q; }
    }
    __syncthreads();
    float mu = red[0] * (1.f / Dd);
    float var = red[1] * (1.f / Dd) - mu * mu;
    float rs = rsqrtf(var + 1e-5f);
#pragma unroll
    for (int t = 0; t < 3; t++) {
        int d = tid + t * 256;
        out[(size_t)row * Dd + d] = (v[t] - mu) * rs * gamma[d] + beta[d];
    }
}

// ---------------- launch ----------------
extern "C" void kernel_launch(void* const* d_in, const int* in_sizes, int n_in,
                              void* d_out, int out_size)
{
    const float* feat  = (const float*)d_in[0];
    const int*   adj   = (const int*)d_in[1];
    const float* Wq    = (const float*)d_in[2];
    const float* bq    = (const float*)d_in[3];
    const float* Wk    = (const float*)d_in[4];
    const float* bk    = (const float*)d_in[5];
    const float* Wv    = (const float*)d_in[6];
    const float* bv    = (const float*)d_in[7];
    const float* gamma = (const float*)d_in[8];
    const float* beta  = (const float*)d_in[9];
    float* out = (float*)d_out;

    float *Qp, *Kp, *Vp;
    cudaGetSymbolAddress((void**)&Qp, g_Q);
    cudaGetSymbolAddress((void**)&Kp, g_K);
    cudaGetSymbolAddress((void**)&Vp, g_V);

    // 1) pack adjacency into bitmask
    {
        size_t n = (size_t)Bb * Ss * Ss;
        pack_mask_kernel<<<(unsigned)(n / 256), 256>>>(adj);
    }

    // 2) QKV projections
    dim3 pgrid(Dd / PBN, M_ROWS / PBM);
    proj_kernel<<<pgrid, 256>>>(feat, Wq, bq, Qp);
    proj_kernel<<<pgrid, 256>>>(feat, Wk, bk, Kp);
    proj_kernel<<<pgrid, 256>>>(feat, Wv, bv, Vp);

    // 3) attention (needs >48KB dynamic smem)
    cudaFuncSetAttribute(attn_kernel, cudaFuncAttributeMaxDynamicSharedMemorySize,
                         ATTN_SMEM_BYTES);
    attn_kernel<<<dim3(Ss / AQ, Hh, Bb), 256, ATTN_SMEM_BYTES>>>(feat);

    // 4) layernorm
    ln_kernel<<<M_ROWS, 256>>>(gamma, beta, out);
}

// round 7
// speedup vs baseline: 1.3635x; 1.0644x over previous
#include <cuda_runtime.h>
#include <math.h>
#include <stdint.h>

#define Bb 8
#define Ss 2048
#define Dd 768
#define Hh 8
#define HD 96
#define M_ROWS (Bb*Ss)          // 16384
#define SW (Ss/32)              // mask words per row = 64

// ---------------- scratch (static device globals; no allocs) ----------------
__device__ float    g_Q[(size_t)Bb*Hh*Ss*HD];
__device__ float    g_K[(size_t)Bb*Hh*Ss*HD];
__device__ float    g_V[(size_t)Bb*Hh*Ss*HD];
__device__ float    g_CTX[(size_t)Bb*Ss*Dd];
__device__ uint32_t g_mask[(size_t)Bb*Ss*SW];

// ---------------- 1) pack adj (int32 0/1) into bitmask ----------------
__global__ void pack_mask_kernel(const int* __restrict__ adj) {
    size_t idx = (size_t)blockIdx.x * blockDim.x + threadIdx.x;
    int v = adj[idx];
    unsigned bits = __ballot_sync(0xffffffffu, v != 0);
    if ((threadIdx.x & 31) == 0) g_mask[idx >> 5] = bits;
}

// ---------------- 2) merged QKV projection: 128x128x8, 8x8 microtile, z picks Q/K/V ----------------
#define PBM 128
#define PBN 128
#define PBK 8
#define PLD 132

__global__ __launch_bounds__(256, 2) void proj_kernel(
    const float* __restrict__ X,   // [M_ROWS, D]
    const float* __restrict__ Wq, const float* __restrict__ bq,
    const float* __restrict__ Wk, const float* __restrict__ bk,
    const float* __restrict__ Wv, const float* __restrict__ bv)
{
    const int z = blockIdx.z;
    const float* W    = (z == 0) ? Wq : (z == 1) ? Wk : Wv;
    const float* bias = (z == 0) ? bq : (z == 1) ? bk : bv;
    float* out        = (z == 0) ? g_Q : (z == 1) ? g_K : g_V;

    __shared__ float As[2][PBK][PLD];
    __shared__ float Bs[2][PBK][PLD];

    const int tid = threadIdx.x;
    const int tr = tid >> 4;          // 0..15
    const int tc = tid & 15;          // 0..15
    const int rowBase = blockIdx.y * PBM;
    const int colBase = blockIdx.x * PBN;

    const int lm = tid >> 1;          // 0..127 (tile row for loading)
    const int lk = (tid & 1) * 4;     // 0 or 4

    const float* Xp = X + (size_t)(rowBase + lm) * Dd + lk;
    const float* Wp = W + (size_t)(colBase + lm) * Dd + lk;

    float acc[8][8];
#pragma unroll
    for (int i = 0; i < 8; i++)
#pragma unroll
        for (int j = 0; j < 8; j++) acc[i][j] = 0.f;

    // preload first tile
    float4 ra = *(const float4*)(Xp + 0);
    float4 rb = *(const float4*)(Wp + 0);
    As[0][lk + 0][lm] = ra.x; As[0][lk + 1][lm] = ra.y;
    As[0][lk + 2][lm] = ra.z; As[0][lk + 3][lm] = ra.w;
    Bs[0][lk + 0][lm] = rb.x; Bs[0][lk + 1][lm] = rb.y;
    Bs[0][lk + 2][lm] = rb.z; Bs[0][lk + 3][lm] = rb.w;
    __syncthreads();

    int buf = 0;
    for (int k0 = 0; k0 < Dd; k0 += PBK) {
        float4 na, nb;
        const bool has_next = (k0 + PBK < Dd);
        if (has_next) {
            na = *(const float4*)(Xp + k0 + PBK);
            nb = *(const float4*)(Wp + k0 + PBK);
        }
#pragma unroll
        for (int kk = 0; kk < PBK; kk++) {
            float4 a0 = *(float4*)&As[buf][kk][tr * 8];
            float4 a1 = *(float4*)&As[buf][kk][tr * 8 + 4];
            float4 b0 = *(float4*)&Bs[buf][kk][tc * 8];
            float4 b1 = *(float4*)&Bs[buf][kk][tc * 8 + 4];
            float a[8] = {a0.x, a0.y, a0.z, a0.w, a1.x, a1.y, a1.z, a1.w};
            float b[8] = {b0.x, b0.y, b0.z, b0.w, b1.x, b1.y, b1.z, b1.w};
#pragma unroll
            for (int i = 0; i < 8; i++)
#pragma unroll
                for (int j = 0; j < 8; j++) acc[i][j] = fmaf(a[i], b[j], acc[i][j]);
        }
        if (has_next) {
            int nb_ = buf ^ 1;
            As[nb_][lk + 0][lm] = na.x; As[nb_][lk + 1][lm] = na.y;
            As[nb_][lk + 2][lm] = na.z; As[nb_][lk + 3][lm] = na.w;
            Bs[nb_][lk + 0][lm] = nb.x; Bs[nb_][lk + 1][lm] = nb.y;
            Bs[nb_][lk + 2][lm] = nb.z; Bs[nb_][lk + 3][lm] = nb.w;
        }
        __syncthreads();
        buf ^= 1;
    }

    float bias8[8];
#pragma unroll
    for (int j = 0; j < 8; j++) bias8[j] = bias[colBase + tc * 8 + j];

#pragma unroll
    for (int i = 0; i < 8; i++) {
        int m = rowBase + tr * 8 + i;
        int b_ = m >> 11, s_ = m & (Ss - 1);
#pragma unroll
        for (int g = 0; g < 2; g++) {
            int n0 = colBase + tc * 8 + g * 4;
            int h_ = n0 / HD, hd = n0 - h_ * HD;   // 4-col group never crosses head (96 % 4 == 0)
            float4 o;
            o.x = acc[i][g * 4 + 0] + bias8[g * 4 + 0];
            o.y = acc[i][g * 4 + 1] + bias8[g * 4 + 1];
            o.z = acc[i][g * 4 + 2] + bias8[g * 4 + 2];
            o.w = acc[i][g * 4 + 3] + bias8[g * 4 + 3];
            *(float4*)&out[(((size_t)b_ * Hh + h_) * Ss + s_) * HD + hd] = o;
        }
    }
}

// ---------------- 3) flash attention v3: register softmax, 3 syncs/iter ----------------
#define AQ 128
#define AKV 128
#define QLD 132     // Qs/Ks stride: [k][q], k<96
#define VLD 104     // Vs stride: [c][hd]
#define SLD 132     // Ssm stride: [r][c]
#define ANKT (Ss / AKV)   // 16

#define ATTN_F (2 * HD * QLD + AKV * VLD + AQ * SLD + AQ * 4)
#define ATTN_SMEM_BYTES (ATTN_F * 4)

__global__ __launch_bounds__(256, 1) void attn_kernel(const float* __restrict__ feat)
{
    extern __shared__ float smem[];
    float* Qs    = smem;                    // [96][132] transposed
    float* Ks    = Qs + HD * QLD;           // [96][132] transposed
    float* Vs    = Ks + HD * QLD;           // [128][104]
    float* Ssm   = Vs + AKV * VLD;          // [128][132] (holds P)
    uint32_t* Ms = (uint32_t*)(Ssm + AQ * SLD);  // [128][4]

    const int tid = threadIdx.x;
    const int qt = blockIdx.x, h = blockIdx.y, b = blockIdx.z;
    const int tr = tid >> 4;   // 0..15 -> rows tr*8..+7
    const int tc = tid & 15;   // 0..15 (16 threads per row-group = half-warp)

    const float* Qg = g_Q + (((size_t)b * Hh + h) * Ss + (size_t)qt * AQ) * HD;
    const float* Kg = g_K + ((size_t)b * Hh + h) * Ss * HD;
    const float* Vg = g_V + ((size_t)b * Hh + h) * Ss * HD;

    // load Q transposed: Qs[k][q]
    for (int i = tid; i < AQ * HD / 4; i += 256) {
        int q = i / 24, hd4 = (i % 24) * 4;
        float4 v = *(const float4*)&Qg[q * HD + hd4];
        Qs[(hd4 + 0) * QLD + q] = v.x;
        Qs[(hd4 + 1) * QLD + q] = v.y;
        Qs[(hd4 + 2) * QLD + q] = v.z;
        Qs[(hd4 + 3) * QLD + q] = v.w;
    }

    float acc[8][6];
#pragma unroll
    for (int i = 0; i < 8; i++)
#pragma unroll
        for (int j = 0; j < 6; j++) acc[i][j] = 0.f;

    // per-row softmax state, replicated across the 16 threads of each row-group
    float m_row[8], l_row[8];
#pragma unroll
    for (int i = 0; i < 8; i++) { m_row[i] = -INFINITY; l_row[i] = 0.f; }

    const float scale = 0.10206207261596577f;   // 1/sqrt(96)

    for (int kt = 0; kt < ANKT; kt++) {
        __syncthreads();   // previous iteration's readers of Ks/Vs/Ssm/Ms done
        const float* Kt = Kg + (size_t)kt * AKV * HD;
        const float* Vt = Vg + (size_t)kt * AKV * HD;
        for (int i = tid; i < AKV * HD / 4; i += 256) {
            int c = i / 24, hd4 = (i % 24) * 4;
            float4 kv = *(const float4*)&Kt[c * HD + hd4];
            Ks[(hd4 + 0) * QLD + c] = kv.x;
            Ks[(hd4 + 1) * QLD + c] = kv.y;
            Ks[(hd4 + 2) * QLD + c] = kv.z;
            Ks[(hd4 + 3) * QLD + c] = kv.w;
            float4 vv = *(const float4*)&Vt[c * HD + hd4];
            *(float4*)&Vs[c * VLD + hd4] = vv;
        }
        for (int i = tid; i < AQ * 4; i += 256)
            Ms[i] = g_mask[((size_t)b * Ss + qt * AQ + (i >> 2)) * SW + kt * 4 + (i & 3)];
        __syncthreads();

        // --- scores: S = Q @ K^T, 8x8 microtile, all-float4 LDS ---
        float sc[8][8];
#pragma unroll
        for (int i = 0; i < 8; i++)
#pragma unroll
            for (int j = 0; j < 8; j++) sc[i][j] = 0.f;
#pragma unroll 2
        for (int k = 0; k < HD; k++) {
            float4 a0 = *(float4*)&Qs[k * QLD + tr * 8];
            float4 a1 = *(float4*)&Qs[k * QLD + tr * 8 + 4];
            float4 b0 = *(float4*)&Ks[k * QLD + tc * 8];
            float4 b1 = *(float4*)&Ks[k * QLD + tc * 8 + 4];
            float a[8] = {a0.x, a0.y, a0.z, a0.w, a1.x, a1.y, a1.z, a1.w};
            float bb[8] = {b0.x, b0.y, b0.z, b0.w, b1.x, b1.y, b1.z, b1.w};
#pragma unroll
            for (int i = 0; i < 8; i++)
#pragma unroll
                for (int j = 0; j < 8; j++) sc[i][j] = fmaf(a[i], bb[j], sc[i][j]);
        }

        // --- mask + scale in registers ---
#pragma unroll
        for (int i = 0; i < 8; i++) {
            int r = tr * 8 + i;
            uint32_t word = Ms[r * 4 + (tc >> 2)];
            int bitbase = (tc & 3) * 8;
#pragma unroll
            for (int j = 0; j < 8; j++)
                sc[i][j] = ((word >> (bitbase + j)) & 1u) ? sc[i][j] * scale : -1e9f;
        }

        // --- register softmax: half-warp shfl reductions ---
        float tmax[8];
#pragma unroll
        for (int i = 0; i < 8; i++)
            tmax[i] = fmaxf(fmaxf(fmaxf(sc[i][0], sc[i][1]), fmaxf(sc[i][2], sc[i][3])),
                            fmaxf(fmaxf(sc[i][4], sc[i][5]), fmaxf(sc[i][6], sc[i][7])));
#pragma unroll
        for (int o = 1; o < 16; o <<= 1)
#pragma unroll
            for (int i = 0; i < 8; i++)
                tmax[i] = fmaxf(tmax[i], __shfl_xor_sync(0xffffffffu, tmax[i], o));

        float alpha[8], rsum[8];
#pragma unroll
        for (int i = 0; i < 8; i++) {
            float m_new = fmaxf(m_row[i], tmax[i]);
            alpha[i] = __expf(m_row[i] - m_new);
            m_row[i] = m_new;
            float s = 0.f;
#pragma unroll
            for (int j = 0; j < 8; j++) {
                float p = __expf(sc[i][j] - m_new);
                sc[i][j] = p;
                s += p;
            }
            rsum[i] = s;
        }
#pragma unroll
        for (int o = 1; o < 16; o <<= 1)
#pragma unroll
            for (int i = 0; i < 8; i++)
                rsum[i] += __shfl_xor_sync(0xffffffffu, rsum[i], o);
#pragma unroll
        for (int i = 0; i < 8; i++)
            l_row[i] = l_row[i] * alpha[i] + rsum[i];

        // --- write P tile ---
#pragma unroll
        for (int i = 0; i < 8; i++) {
            int r = tr * 8 + i;
            float4 s0 = {sc[i][0], sc[i][1], sc[i][2], sc[i][3]};
            float4 s1 = {sc[i][4], sc[i][5], sc[i][6], sc[i][7]};
            *(float4*)&Ssm[r * SLD + tc * 8]     = s0;
            *(float4*)&Ssm[r * SLD + tc * 8 + 4] = s1;
        }
        __syncthreads();

        // --- rescale acc (register alpha), then O += P @ V ---
#pragma unroll
        for (int i = 0; i < 8; i++)
#pragma unroll
            for (int j = 0; j < 6; j++) acc[i][j] *= alpha[i];

        for (int c0 = 0; c0 < AKV; c0 += 4) {
            float pr[8][4];
#pragma unroll
            for (int i = 0; i < 8; i++) {
                float4 t = *(float4*)&Ssm[(tr * 8 + i) * SLD + c0];
                pr[i][0] = t.x; pr[i][1] = t.y; pr[i][2] = t.z; pr[i][3] = t.w;
            }
#pragma unroll
            for (int cc = 0; cc < 4; cc++) {
                const float* Vr = Vs + (c0 + cc) * VLD + tc * 6;
                float2 v0 = *(float2*)&Vr[0];
                float2 v1 = *(float2*)&Vr[2];
                float2 v2 = *(float2*)&Vr[4];
                float v[6] = {v0.x, v0.y, v1.x, v1.y, v2.x, v2.y};
#pragma unroll
                for (int i = 0; i < 8; i++) {
                    float p = pr[i][cc];
#pragma unroll
                    for (int j = 0; j < 6; j++) acc[i][j] = fmaf(p, v[j], acc[i][j]);
                }
            }
        }
    }

    // --- epilogue: ctx = O/l + residual ---
#pragma unroll
    for (int i = 0; i < 8; i++) {
        int r = tr * 8 + i;
        int q = qt * AQ + r;
        float invl = 1.f / l_row[i];
        size_t base = ((size_t)b * Ss + q) * Dd + h * HD + tc * 6;
#pragma unroll
        for (int j = 0; j < 6; j++)
            g_CTX[base + j] = acc[i][j] * invl + feat[base + j];
    }
}

// ---------------- 4) LayerNorm over D=768 ----------------
__global__ __launch_bounds__(256) void ln_kernel(
    const float* __restrict__ gamma, const float* __restrict__ beta,
    float* __restrict__ out)
{
    __shared__ float red[16];
    const int row = blockIdx.x;
    const int tid = threadIdx.x;
    const float* x = g_CTX + (size_t)row * Dd;

    float v[3];
    float sum = 0.f, sq = 0.f;
#pragma unroll
    for (int t = 0; t < 3; t++) {
        v[t] = x[tid + t * 256];
        sum += v[t];
        sq  = fmaf(v[t], v[t], sq);
    }
#pragma unroll
    for (int o = 16; o > 0; o >>= 1) {
        sum += __shfl_xor_sync(0xffffffffu, sum, o);
        sq  += __shfl_xor_sync(0xffffffffu, sq, o);
    }
    int warp = tid >> 5;
    if ((tid & 31) == 0) { red[warp] = sum; red[warp + 8] = sq; }
    __syncthreads();
    if (tid < 32) {
        float s = (tid < 8) ? red[tid] : 0.f;
        float q = (tid < 8) ? red[tid + 8] : 0.f;
#pragma unroll
        for (int o = 4; o > 0; o >>= 1) {
            s += __shfl_xor_sync(0xffffffffu, s, o);
            q += __shfl_xor_sync(0xffffffffu, q, o);
        }
        if (tid == 0) { red[0] = s; red[1] = q; }
    }
    __syncthreads();
    float mu = red[0] * (1.f / Dd);
    float var = red[1] * (1.f / Dd) - mu * mu;
    float rs = rsqrtf(var + 1e-5f);
#pragma unroll
    for (int t = 0; t < 3; t++) {
        int d = tid + t * 256;
        out[(size_t)row * Dd + d] = (v[t] - mu) * rs * gamma[d] + beta[d];
    }
}

// ---------------- launch ----------------
extern "C" void kernel_launch(void* const* d_in, const int* in_sizes, int n_in,
                              void* d_out, int out_size)
{
    const float* feat  = (const float*)d_in[0];
    const int*   adj   = (const int*)d_in[1];
    const float* Wq    = (const float*)d_in[2];
    const float* bq    = (const float*)d_in[3];
    const float* Wk    = (const float*)d_in[4];
    const float* bk    = (const float*)d_in[5];
    const float* Wv    = (const float*)d_in[6];
    const float* bv    = (const float*)d_in[7];
    const float* gamma = (const float*)d_in[8];
    const float* beta  = (const float*)d_in[9];
    float* out = (float*)d_out;

    // 1) pack adjacency into bitmask
    {
        size_t n = (size_t)Bb * Ss * Ss;
        pack_mask_kernel<<<(unsigned)(n / 256), 256>>>(adj);
    }

    // 2) QKV projections (single launch, z selects Q/K/V)
    dim3 pgrid(Dd / PBN, M_ROWS / PBM, 3);
    proj_kernel<<<pgrid, 256>>>(feat, Wq, bq, Wk, bk, Wv, bv);

    // 3) attention (needs >48KB dynamic smem)
    cudaFuncSetAttribute(attn_kernel, cudaFuncAttributeMaxDynamicSharedMemorySize,
                         ATTN_SMEM_BYTES);
    attn_kernel<<<dim3(Ss / AQ, Hh, Bb), 256, ATTN_SMEM_BYTES>>>(feat);

    // 4) layernorm
    ln_kernel<<<M_ROWS, 256>>>(gamma, beta, out);
}

// round 9
// speedup vs baseline: 1.9766x; 1.4497x over previous
#include <cuda_runtime.h>
#include <math.h>
#include <stdint.h>

#define Bb 8
#define Ss 2048
#define Dd 768
#define Hh 8
#define HD 96
#define M_ROWS (Bb*Ss)          // 16384
#define SW (Ss/32)              // mask words per row = 64

// ---------------- scratch (static device globals; no allocs) ----------------
__device__ float    g_Q[(size_t)Bb*Hh*Ss*HD];
__device__ float    g_K[(size_t)Bb*Hh*Ss*HD];
__device__ float    g_V[(size_t)Bb*Hh*Ss*HD];
__device__ float    g_CTX[(size_t)Bb*Ss*Dd];
__device__ uint32_t g_mask[(size_t)Bb*Ss*SW];

// ---------------- 1) pack adj (int32 0/1) into bitmask ----------------
__global__ void pack_mask_kernel(const int* __restrict__ adj) {
    size_t idx = (size_t)blockIdx.x * blockDim.x + threadIdx.x;
    int v = adj[idx];
    unsigned bits = __ballot_sync(0xffffffffu, v != 0);
    if ((threadIdx.x & 31) == 0) g_mask[idx >> 5] = bits;
}

// ---------------- 2) merged QKV projection: 128x128x8, 8x8 microtile, z picks Q/K/V ----------------
#define PBM 128
#define PBN 128
#define PBK 8
#define PLD 132

__global__ __launch_bounds__(256, 2) void proj_kernel(
    const float* __restrict__ X,
    const float* __restrict__ Wq, const float* __restrict__ bq,
    const float* __restrict__ Wk, const float* __restrict__ bk,
    const float* __restrict__ Wv, const float* __restrict__ bv)
{
    const int z = blockIdx.z;
    const float* W    = (z == 0) ? Wq : (z == 1) ? Wk : Wv;
    const float* bias = (z == 0) ? bq : (z == 1) ? bk : bv;
    float* out        = (z == 0) ? g_Q : (z == 1) ? g_K : g_V;

    __shared__ float As[2][PBK][PLD];
    __shared__ float Bs[2][PBK][PLD];

    const int tid = threadIdx.x;
    const int tr = tid >> 4;
    const int tc = tid & 15;
    const int rowBase = blockIdx.y * PBM;
    const int colBase = blockIdx.x * PBN;

    const int lm = tid >> 1;
    const int lk = (tid & 1) * 4;

    const float* Xp = X + (size_t)(rowBase + lm) * Dd + lk;
    const float* Wp = W + (size_t)(colBase + lm) * Dd + lk;

    float acc[8][8];
#pragma unroll
    for (int i = 0; i < 8; i++)
#pragma unroll
        for (int j = 0; j < 8; j++) acc[i][j] = 0.f;

    float4 ra = *(const float4*)(Xp + 0);
    float4 rb = *(const float4*)(Wp + 0);
    As[0][lk + 0][lm] = ra.x; As[0][lk + 1][lm] = ra.y;
    As[0][lk + 2][lm] = ra.z; As[0][lk + 3][lm] = ra.w;
    Bs[0][lk + 0][lm] = rb.x; Bs[0][lk + 1][lm] = rb.y;
    Bs[0][lk + 2][lm] = rb.z; Bs[0][lk + 3][lm] = rb.w;
    __syncthreads();

    int buf = 0;
    for (int k0 = 0; k0 < Dd; k0 += PBK) {
        float4 na, nb;
        const bool has_next = (k0 + PBK < Dd);
        if (has_next) {
            na = *(const float4*)(Xp + k0 + PBK);
            nb = *(const float4*)(Wp + k0 + PBK);
        }
#pragma unroll
        for (int kk = 0; kk < PBK; kk++) {
            float4 a0 = *(float4*)&As[buf][kk][tr * 8];
            float4 a1 = *(float4*)&As[buf][kk][tr * 8 + 4];
            float4 b0 = *(float4*)&Bs[buf][kk][tc * 8];
            float4 b1 = *(float4*)&Bs[buf][kk][tc * 8 + 4];
            float a[8] = {a0.x, a0.y, a0.z, a0.w, a1.x, a1.y, a1.z, a1.w};
            float b[8] = {b0.x, b0.y, b0.z, b0.w, b1.x, b1.y, b1.z, b1.w};
#pragma unroll
            for (int i = 0; i < 8; i++)
#pragma unroll
                for (int j = 0; j < 8; j++) acc[i][j] = fmaf(a[i], b[j], acc[i][j]);
        }
        if (has_next) {
            int nb_ = buf ^ 1;
            As[nb_][lk + 0][lm] = na.x; As[nb_][lk + 1][lm] = na.y;
            As[nb_][lk + 2][lm] = na.z; As[nb_][lk + 3][lm] = na.w;
            Bs[nb_][lk + 0][lm] = nb.x; Bs[nb_][lk + 1][lm] = nb.y;
            Bs[nb_][lk + 2][lm] = nb.z; Bs[nb_][lk + 3][lm] = nb.w;
        }
        __syncthreads();
        buf ^= 1;
    }

    float bias8[8];
#pragma unroll
    for (int j = 0; j < 8; j++) bias8[j] = bias[colBase + tc * 8 + j];

#pragma unroll
    for (int i = 0; i < 8; i++) {
        int m = rowBase + tr * 8 + i;
        int b_ = m >> 11, s_ = m & (Ss - 1);
#pragma unroll
        for (int g = 0; g < 2; g++) {
            int n0 = colBase + tc * 8 + g * 4;
            int h_ = n0 / HD, hd = n0 - h_ * HD;
            float4 o;
            o.x = acc[i][g * 4 + 0] + bias8[g * 4 + 0];
            o.y = acc[i][g * 4 + 1] + bias8[g * 4 + 1];
            o.z = acc[i][g * 4 + 2] + bias8[g * 4 + 2];
            o.w = acc[i][g * 4 + 3] + bias8[g * 4 + 3];
            *(float4*)&out[(((size_t)b_ * Hh + h_) * Ss + s_) * HD + hd] = o;
        }
    }
}

// ---------------- 3) flash attention v4: mma.sync tf32 tensor cores ----------------
#define AQ 128
#define AKV 128
#define LDK 104     // Ks [kv][hd''] stride (96 -> 104, 104 % 32 == 8)
#define LDV 136     // Vst [hd][kv''] stride (128 -> 136)
#define LDP 136     // Ps  [q][kv''] stride
#define ANKT (Ss / AKV)   // 16

// smem: Ks 128*104 + Vst 96*136 + Ps 128*136 + Ms 512 words
#define ATTN_WORDS (AKV * LDK + HD * LDV + AQ * LDP + AQ * 4)
#define ATTN_SMEM_BYTES (ATTN_WORDS * 4)

__device__ __forceinline__ uint32_t f2tf32(float x) {
    uint32_t r;
    asm("cvt.rna.tf32.f32 %0, %1;" : "=r"(r) : "f"(x));
    return r;
}

__device__ __forceinline__ void mma_tf32(float* c,
    uint32_t a0, uint32_t a1, uint32_t a2, uint32_t a3,
    uint32_t b0, uint32_t b1)
{
    asm volatile(
        "mma.sync.aligned.m16n8k8.row.col.f32.tf32.tf32.f32 "
        "{%0,%1,%2,%3}, {%4,%5,%6,%7}, {%8,%9}, {%0,%1,%2,%3};"
        : "+f"(c[0]), "+f"(c[1]), "+f"(c[2]), "+f"(c[3])
        : "r"(a0), "r"(a1), "r"(a2), "r"(a3), "r"(b0), "r"(b1));
}

__global__ __launch_bounds__(256, 1) void attn_kernel(const float* __restrict__ feat)
{
    extern __shared__ float smem[];
    float* Ks    = smem;                 // [128][104]  K as [kv][perm(hd)]
    float* Vst   = Ks + AKV * LDK;       // [96][136]   V^T as [hd][perm(kv)]
    float* Ps    = Vst + HD * LDV;       // [128][136]  P as [q][perm(kv)]
    uint32_t* Ms = (uint32_t*)(Ps + AQ * LDP);   // [128][4]

    const int tid  = threadIdx.x;
    const int wid  = tid >> 5;
    const int lane = tid & 31;
    const int g    = lane >> 2;          // groupID 0..7
    const int tg   = lane & 3;           // threadID in group 0..3
    const int qt = blockIdx.x, h = blockIdx.y, b = blockIdx.z;
    const int qbase = wid * 16;          // warp's 16 q rows within tile

    const float* Qg = g_Q + (((size_t)b * Hh + h) * Ss + (size_t)qt * AQ) * HD;
    const float* Kg = g_K + ((size_t)b * Hh + h) * Ss * HD;
    const float* Vg = g_V + ((size_t)b * Hh + h) * Ss * HD;

    const int row0 = qbase + g;          // local q rows this thread touches
    const int row1 = row0 + 8;
    const float scale = 0.10206207261596577f;   // 1/sqrt(96)

    // Q held in registers as tf32 A-fragments, pre-scaled. 12 k-steps x 4 regs.
    uint32_t qa[12][4];
#pragma unroll
    for (int s = 0; s < 12; s++) {
        int k0 = s * 8;
        qa[s][0] = f2tf32(Qg[row0 * HD + k0 + tg]     * scale);
        qa[s][1] = f2tf32(Qg[row1 * HD + k0 + tg]     * scale);
        qa[s][2] = f2tf32(Qg[row0 * HD + k0 + tg + 4] * scale);
        qa[s][3] = f2tf32(Qg[row1 * HD + k0 + tg + 4] * scale);
    }

    // PV accumulators: 12 hd-tiles x 4 (rows g,g+8 / cols 2tg,2tg+1)
    float acc[12][4];
#pragma unroll
    for (int t = 0; t < 12; t++)
#pragma unroll
        for (int j = 0; j < 4; j++) acc[t][j] = 0.f;

    float l0 = 0.f, l1 = 0.f;            // unnormalized row sums (no-max softmax)

    const int pos0 = (((2 * tg) & 3) << 1) | (tg >> 1);   // perm position of col 2tg
    const int pos1 = pos0 + 2;                             // perm position of col 2tg+1

    for (int kt = 0; kt < ANKT; kt++) {
        __syncthreads();   // prior readers of Ks/Vst/Ms done

        // ---- load K,V tile with k-pair interleave + tf32 rounding ----
        const float4* Kt4 = (const float4*)(Kg + (size_t)kt * AKV * HD);
        const float4* Vt4 = (const float4*)(Vg + (size_t)kt * AKV * HD);
        for (int i = tid; i < AKV * HD / 4; i += 256) {
            int kv = i / 24, m4 = i % 24;
            float4 kx = Kt4[i];
            int kb = kv * LDK + (m4 >> 1) * 8 + (m4 & 1);   // perm(hd): (k&3)<<1 | k>>2&1
            Ks[kb + 0] = __uint_as_float(f2tf32(kx.x));
            Ks[kb + 2] = __uint_as_float(f2tf32(kx.y));
            Ks[kb + 4] = __uint_as_float(f2tf32(kx.z));
            Ks[kb + 6] = __uint_as_float(f2tf32(kx.w));
            float4 vx = Vt4[i];
            int vcol = (kv & ~7) + (((kv & 3) << 1) | ((kv >> 2) & 1));
            int hd0 = m4 * 4;
            Vst[(hd0 + 0) * LDV + vcol] = __uint_as_float(f2tf32(vx.x));
            Vst[(hd0 + 1) * LDV + vcol] = __uint_as_float(f2tf32(vx.y));
            Vst[(hd0 + 2) * LDV + vcol] = __uint_as_float(f2tf32(vx.z));
            Vst[(hd0 + 3) * LDV + vcol] = __uint_as_float(f2tf32(vx.w));
        }
        for (int i = tid; i < AQ * 4; i += 256)
            Ms[i] = g_mask[((size_t)b * Ss + qt * AQ + (i >> 2)) * SW + kt * 4 + (i & 3)];
        __syncthreads();

        // ---- QK^T: 16 kv-tiles x 12 k-steps of m16n8k8 ----
        float sc[16][4];
#pragma unroll
        for (int t = 0; t < 16; t++)
#pragma unroll
            for (int j = 0; j < 4; j++) sc[t][j] = 0.f;
#pragma unroll
        for (int s = 0; s < 12; s++) {
#pragma unroll
            for (int t = 0; t < 16; t++) {
                uint2 bb = *(const uint2*)&Ks[(t * 8 + g) * LDK + s * 8 + 2 * tg];
                mma_tf32(sc[t], qa[s][0], qa[s][1], qa[s][2], qa[s][3], bb.x, bb.y);
            }
        }

        // ---- mask + exp (no max subtraction), write P (tf32) to warp-private rows ----
        uint32_t mw0[4], mw1[4];
#pragma unroll
        for (int w = 0; w < 4; w++) {
            mw0[w] = Ms[row0 * 4 + w];
            mw1[w] = Ms[row1 * 4 + w];
        }
#pragma unroll
        for (int t = 0; t < 16; t++) {
            int bit0 = 8 * (t & 3) + 2 * tg;
            uint32_t w0 = mw0[t >> 2], w1 = mw1[t >> 2];
            float p0 = 0.f, p1 = 0.f, p2 = 0.f, p3 = 0.f;
            if ((w0 >> bit0) & 1u)       p0 = __expf(sc[t][0]);
            if ((w0 >> (bit0 + 1)) & 1u) p1 = __expf(sc[t][1]);
            if ((w1 >> bit0) & 1u)       p2 = __expf(sc[t][2]);
            if ((w1 >> (bit0 + 1)) & 1u) p3 = __expf(sc[t][3]);
            p0 = __uint_as_float(f2tf32(p0));
            p1 = __uint_as_float(f2tf32(p1));
            p2 = __uint_as_float(f2tf32(p2));
            p3 = __uint_as_float(f2tf32(p3));
            l0 += p0 + p1;
            l1 += p2 + p3;
            int cb = t * 8;
            Ps[row0 * LDP + cb + pos0] = p0;
            Ps[row0 * LDP + cb + pos1] = p1;
            Ps[row1 * LDP + cb + pos0] = p2;
            Ps[row1 * LDP + cb + pos1] = p3;
        }
        __syncwarp();   // P rows are warp-private; only warp-level visibility needed

        // ---- PV: O += P @ V  (16 kv-steps x 12 hd-tiles) ----
#pragma unroll
        for (int s = 0; s < 16; s++) {
            uint2 a02 = *(const uint2*)&Ps[row0 * LDP + s * 8 + 2 * tg];
            uint2 a13 = *(const uint2*)&Ps[row1 * LDP + s * 8 + 2 * tg];
#pragma unroll
            for (int t = 0; t < 12; t++) {
                uint2 bb = *(const uint2*)&Vst[(t * 8 + g) * LDV + s * 8 + 2 * tg];
                mma_tf32(acc[t], a02.x, a13.x, a02.y, a13.y, bb.x, bb.y);
            }
        }
    }

    // ---- finalize: reduce l over quad, normalize, fuse residual ----
    l0 += __shfl_xor_sync(0xffffffffu, l0, 1);
    l0 += __shfl_xor_sync(0xffffffffu, l0, 2);
    l1 += __shfl_xor_sync(0xffffffffu, l1, 1);
    l1 += __shfl_xor_sync(0xffffffffu, l1, 2);
    float il0 = 1.f / l0, il1 = 1.f / l1;

    int q0 = qt * AQ + row0;
    size_t base0 = ((size_t)b * Ss + q0) * Dd + h * HD;
    size_t base1 = base0 + (size_t)8 * Dd;
#pragma unroll
    for (int t = 0; t < 12; t++) {
        int c = t * 8 + 2 * tg;
        float2 f0 = *(const float2*)&feat[base0 + c];
        float2 o0 = {acc[t][0] * il0 + f0.x, acc[t][1] * il0 + f0.y};
        *(float2*)&g_CTX[base0 + c] = o0;
        float2 f1 = *(const float2*)&feat[base1 + c];
        float2 o1 = {acc[t][2] * il1 + f1.x, acc[t][3] * il1 + f1.y};
        *(float2*)&g_CTX[base1 + c] = o1;
    }
}

// ---------------- 4) LayerNorm over D=768 ----------------
__global__ __launch_bounds__(256) void ln_kernel(
    const float* __restrict__ gamma, const float* __restrict__ beta,
    float* __restrict__ out)
{
    __shared__ float red[16];
    const int row = blockIdx.x;
    const int tid = threadIdx.x;
    const float* x = g_CTX + (size_t)row * Dd;

    float v[3];
    float sum = 0.f, sq = 0.f;
#pragma unroll
    for (int t = 0; t < 3; t++) {
        v[t] = x[tid + t * 256];
        sum += v[t];
        sq  = fmaf(v[t], v[t], sq);
    }
#pragma unroll
    for (int o = 16; o > 0; o >>= 1) {
        sum += __shfl_xor_sync(0xffffffffu, sum, o);
        sq  += __shfl_xor_sync(0xffffffffu, sq, o);
    }
    int warp = tid >> 5;
    if ((tid & 31) == 0) { red[warp] = sum; red[warp + 8] = sq; }
    __syncthreads();
    if (tid < 32) {
        float s = (tid < 8) ? red[tid] : 0.f;
        float q = (tid < 8) ? red[tid + 8] : 0.f;
#pragma unroll
        for (int o = 4; o > 0; o >>= 1) {
            s += __shfl_xor_sync(0xffffffffu, s, o);
            q += __shfl_xor_sync(0xffffffffu, q, o);
        }
        if (tid == 0) { red[0] = s; red[1] = q; }
    }
    __syncthreads();
    float mu = red[0] * (1.f / Dd);
    float var = red[1] * (1.f / Dd) - mu * mu;
    float rs = rsqrtf(var + 1e-5f);
#pragma unroll
    for (int t = 0; t < 3; t++) {
        int d = tid + t * 256;
        out[(size_t)row * Dd + d] = (v[t] - mu) * rs * gamma[d] + beta[d];
    }
}

// ---------------- launch ----------------
extern "C" void kernel_launch(void* const* d_in, const int* in_sizes, int n_in,
                              void* d_out, int out_size)
{
    const float* feat  = (const float*)d_in[0];
    const int*   adj   = (const int*)d_in[1];
    const float* Wq    = (const float*)d_in[2];
    const float* bq    = (const float*)d_in[3];
    const float* Wk    = (const float*)d_in[4];
    const float* bk    = (const float*)d_in[5];
    const float* Wv    = (const float*)d_in[6];
    const float* bv    = (const float*)d_in[7];
    const float* gamma = (const float*)d_in[8];
    const float* beta  = (const float*)d_in[9];
    float* out = (float*)d_out;

    // 1) pack adjacency into bitmask
    {
        size_t n = (size_t)Bb * Ss * Ss;
        pack_mask_kernel<<<(unsigned)(n / 256), 256>>>(adj);
    }

    // 2) QKV projections (single launch, z selects Q/K/V)
    dim3 pgrid(Dd / PBN, M_ROWS / PBM, 3);
    proj_kernel<<<pgrid, 256>>>(feat, Wq, bq, Wk, bk, Wv, bv);

    // 3) attention (tf32 tensor cores; >48KB dynamic smem)
    cudaFuncSetAttribute(attn_kernel, cudaFuncAttributeMaxDynamicSharedMemorySize,
                         ATTN_SMEM_BYTES);
    attn_kernel<<<dim3(Ss / AQ, Hh, Bb), 256, ATTN_SMEM_BYTES>>>(feat);

    // 4) layernorm
    ln_kernel<<<M_ROWS, 256>>>(gamma, beta, out);
}

// round 10
// speedup vs baseline: 2.6191x; 1.3250x over previous
#include <cuda_runtime.h>
#include <math.h>
#include <stdint.h>

#define Bb 8
#define Ss 2048
#define Dd 768
#define Hh 8
#define HD 96
#define M_ROWS (Bb*Ss)          // 16384
#define SW (Ss/32)              // mask words per row = 64

// ---------------- scratch (static device globals; no allocs) ----------------
__device__ float    g_Q[(size_t)Bb*Hh*Ss*HD];
__device__ float    g_K[(size_t)Bb*Hh*Ss*HD];
__device__ float    g_V[(size_t)Bb*Hh*Ss*HD];
__device__ float    g_CTX[(size_t)Bb*Ss*Dd];
__device__ uint32_t g_mask[(size_t)Bb*Ss*SW];

__device__ __forceinline__ uint32_t f2tf32(float x) {
    uint32_t r;
    asm("cvt.rna.tf32.f32 %0, %1;" : "=r"(r) : "f"(x));
    return r;
}

__device__ __forceinline__ void mma_tf32(float* c,
    uint32_t a0, uint32_t a1, uint32_t a2, uint32_t a3,
    uint32_t b0, uint32_t b1)
{
    asm volatile(
        "mma.sync.aligned.m16n8k8.row.col.f32.tf32.tf32.f32 "
        "{%0,%1,%2,%3}, {%4,%5,%6,%7}, {%8,%9}, {%0,%1,%2,%3};"
        : "+f"(c[0]), "+f"(c[1]), "+f"(c[2]), "+f"(c[3])
        : "r"(a0), "r"(a1), "r"(a2), "r"(a3), "r"(b0), "r"(b1));
}

// ---------------- 1) pack adj (int32 0/1) into bitmask ----------------
__global__ void pack_mask_kernel(const int* __restrict__ adj) {
    size_t idx = (size_t)blockIdx.x * blockDim.x + threadIdx.x;
    int v = adj[idx];
    unsigned bits = __ballot_sync(0xffffffffu, v != 0);
    if ((threadIdx.x & 31) == 0) g_mask[idx >> 5] = bits;
}

// ---------------- 2) merged QKV projection: tf32 mma, 128x128x32 tiles ----------------
#define PLDX 40    // smem stride: 32 k-floats + pad, 40 % 32 == 8

__global__ __launch_bounds__(256, 2) void proj_kernel(
    const float* __restrict__ X,
    const float* __restrict__ Wq, const float* __restrict__ bq,
    const float* __restrict__ Wk, const float* __restrict__ bk,
    const float* __restrict__ Wv, const float* __restrict__ bv)
{
    const int z = blockIdx.z;
    const float* W    = (z == 0) ? Wq : (z == 1) ? Wk : Wv;
    const float* bias = (z == 0) ? bq : (z == 1) ? bk : bv;
    float* out        = (z == 0) ? g_Q : (z == 1) ? g_K : g_V;

    __shared__ float Xs[128 * PLDX];
    __shared__ float Ws[128 * PLDX];

    const int tid  = threadIdx.x;
    const int wid  = tid >> 5;
    const int lane = tid & 31;
    const int g    = lane >> 2;
    const int tg   = lane & 3;

    const int rowBase = blockIdx.y * 128;
    const int colBase = blockIdx.x * 128;

    // warp tiling: 4 m-groups x 2 n-groups; each warp 32 rows x 64 cols
    const int mbase  = (wid >> 1) * 32;
    const int nwbase = (wid & 1) * 64;
    const int row0 = mbase + g;          // + 0, 8, 16, 24

    float sc0[8][4], sc1[8][4];
#pragma unroll
    for (int t = 0; t < 8; t++)
#pragma unroll
        for (int j = 0; j < 4; j++) { sc0[t][j] = 0.f; sc1[t][j] = 0.f; }

    float4 xr[4], wr[4];

    // prefetch chunk 0
#pragma unroll
    for (int i = 0; i < 4; i++) {
        int sl = tid + i * 256, row = sl >> 3, j = sl & 7;
        xr[i] = *(const float4*)&X[(size_t)(rowBase + row) * Dd + j * 4];
        wr[i] = *(const float4*)&W[(size_t)(colBase + row) * Dd + j * 4];
    }
    // store chunk 0 (k-pair interleave + tf32 cvt)
#pragma unroll
    for (int i = 0; i < 4; i++) {
        int sl = tid + i * 256, row = sl >> 3, j = sl & 7;
        int base = row * PLDX + (j >> 1) * 8 + (j & 1);
        Xs[base + 0] = __uint_as_float(f2tf32(xr[i].x));
        Xs[base + 2] = __uint_as_float(f2tf32(xr[i].y));
        Xs[base + 4] = __uint_as_float(f2tf32(xr[i].z));
        Xs[base + 6] = __uint_as_float(f2tf32(xr[i].w));
        Ws[base + 0] = __uint_as_float(f2tf32(wr[i].x));
        Ws[base + 2] = __uint_as_float(f2tf32(wr[i].y));
        Ws[base + 4] = __uint_as_float(f2tf32(wr[i].z));
        Ws[base + 6] = __uint_as_float(f2tf32(wr[i].w));
    }
    __syncthreads();

    const int NCHUNK = Dd / 32;   // 24
    for (int c = 0; c < NCHUNK; c++) {
        const bool has_next = (c + 1 < NCHUNK);
        if (has_next) {
            int k0 = (c + 1) * 32;
#pragma unroll
            for (int i = 0; i < 4; i++) {
                int sl = tid + i * 256, row = sl >> 3, j = sl & 7;
                xr[i] = *(const float4*)&X[(size_t)(rowBase + row) * Dd + k0 + j * 4];
                wr[i] = *(const float4*)&W[(size_t)(colBase + row) * Dd + k0 + j * 4];
            }
        }

        // compute 4 k8-steps from smem
#pragma unroll
        for (int s = 0; s < 4; s++) {
            uint2 xa0 = *(const uint2*)&Xs[(row0 +  0) * PLDX + s * 8 + 2 * tg];
            uint2 xa1 = *(const uint2*)&Xs[(row0 +  8) * PLDX + s * 8 + 2 * tg];
            uint2 xa2 = *(const uint2*)&Xs[(row0 + 16) * PLDX + s * 8 + 2 * tg];
            uint2 xa3 = *(const uint2*)&Xs[(row0 + 24) * PLDX + s * 8 + 2 * tg];
#pragma unroll
            for (int t = 0; t < 8; t++) {
                uint2 bb = *(const uint2*)&Ws[(nwbase + t * 8 + g) * PLDX + s * 8 + 2 * tg];
                mma_tf32(sc0[t], xa0.x, xa1.x, xa0.y, xa1.y, bb.x, bb.y);
                mma_tf32(sc1[t], xa2.x, xa3.x, xa2.y, xa3.y, bb.x, bb.y);
            }
        }

        if (has_next) {
            __syncthreads();
#pragma unroll
            for (int i = 0; i < 4; i++) {
                int sl = tid + i * 256, row = sl >> 3, j = sl & 7;
                int base = row * PLDX + (j >> 1) * 8 + (j & 1);
                Xs[base + 0] = __uint_as_float(f2tf32(xr[i].x));
                Xs[base + 2] = __uint_as_float(f2tf32(xr[i].y));
                Xs[base + 4] = __uint_as_float(f2tf32(xr[i].z));
                Xs[base + 6] = __uint_as_float(f2tf32(xr[i].w));
                Ws[base + 0] = __uint_as_float(f2tf32(wr[i].x));
                Ws[base + 2] = __uint_as_float(f2tf32(wr[i].y));
                Ws[base + 4] = __uint_as_float(f2tf32(wr[i].z));
                Ws[base + 6] = __uint_as_float(f2tf32(wr[i].w));
            }
            __syncthreads();
        }
    }

    // ---- epilogue: bias + scatter to [B,H,S,HD], float2 stores ----
#pragma unroll
    for (int t = 0; t < 8; t++) {
        int n0 = colBase + nwbase + t * 8 + 2 * tg;
        int h_ = n0 / HD, hd = n0 - h_ * HD;        // n0 even; pair stays in head
        float2 bs = {bias[n0], bias[n0 + 1]};
#pragma unroll
        for (int mt = 0; mt < 4; mt++) {
            int m = rowBase + row0 + mt * 8;
            int b_ = m >> 11, s_ = m & (Ss - 1);
            const float* a = (mt < 2) ? sc0[t] : sc1[t];
            int o = (mt & 1) * 2;
            float2 v = {a[o] + bs.x, a[o + 1] + bs.y};
            *(float2*)&out[(((size_t)b_ * Hh + h_) * Ss + s_) * HD + hd] = v;
        }
    }
}

// ---------------- 3) flash attention v4: mma.sync tf32 tensor cores ----------------
#define AQ 128
#define AKV 128
#define LDK 104     // Ks [kv][hd''] stride
#define LDV 136     // Vst [hd][kv''] stride
#define LDP 136     // Ps  [q][kv''] stride
#define ANKT (Ss / AKV)   // 16

#define ATTN_WORDS (AKV * LDK + HD * LDV + AQ * LDP + AQ * 4)
#define ATTN_SMEM_BYTES (ATTN_WORDS * 4)

__global__ __launch_bounds__(256, 1) void attn_kernel(const float* __restrict__ feat)
{
    extern __shared__ float smem[];
    float* Ks    = smem;                 // [128][104]  K as [kv][perm(hd)]
    float* Vst   = Ks + AKV * LDK;       // [96][136]   V^T as [hd][perm(kv)]
    float* Ps    = Vst + HD * LDV;       // [128][136]  P as [q][perm(kv)]
    uint32_t* Ms = (uint32_t*)(Ps + AQ * LDP);   // [128][4]

    const int tid  = threadIdx.x;
    const int wid  = tid >> 5;
    const int lane = tid & 31;
    const int g    = lane >> 2;
    const int tg   = lane & 3;
    const int qt = blockIdx.x, h = blockIdx.y, b = blockIdx.z;
    const int qbase = wid * 16;

    const float* Qg = g_Q + (((size_t)b * Hh + h) * Ss + (size_t)qt * AQ) * HD;
    const float* Kg = g_K + ((size_t)b * Hh + h) * Ss * HD;
    const float* Vg = g_V + ((size_t)b * Hh + h) * Ss * HD;

    const int row0 = qbase + g;
    const int row1 = row0 + 8;
    const float scale = 0.10206207261596577f;   // 1/sqrt(96)

    uint32_t qa[12][4];
#pragma unroll
    for (int s = 0; s < 12; s++) {
        int k0 = s * 8;
        qa[s][0] = f2tf32(Qg[row0 * HD + k0 + tg]     * scale);
        qa[s][1] = f2tf32(Qg[row1 * HD + k0 + tg]     * scale);
        qa[s][2] = f2tf32(Qg[row0 * HD + k0 + tg + 4] * scale);
        qa[s][3] = f2tf32(Qg[row1 * HD + k0 + tg + 4] * scale);
    }

    float acc[12][4];
#pragma unroll
    for (int t = 0; t < 12; t++)
#pragma unroll
        for (int j = 0; j < 4; j++) acc[t][j] = 0.f;

    float l0 = 0.f, l1 = 0.f;

    const int pos0 = (((2 * tg) & 3) << 1) | (tg >> 1);
    const int pos1 = pos0 + 2;

    for (int kt = 0; kt < ANKT; kt++) {
        __syncthreads();

        const float4* Kt4 = (const float4*)(Kg + (size_t)kt * AKV * HD);
        const float4* Vt4 = (const float4*)(Vg + (size_t)kt * AKV * HD);
        for (int i = tid; i < AKV * HD / 4; i += 256) {
            int kv = i / 24, m4 = i % 24;
            float4 kx = Kt4[i];
            int kb = kv * LDK + (m4 >> 1) * 8 + (m4 & 1);
            Ks[kb + 0] = __uint_as_float(f2tf32(kx.x));
            Ks[kb + 2] = __uint_as_float(f2tf32(kx.y));
            Ks[kb + 4] = __uint_as_float(f2tf32(kx.z));
            Ks[kb + 6] = __uint_as_float(f2tf32(kx.w));
            float4 vx = Vt4[i];
            int vcol = (kv & ~7) + (((kv & 3) << 1) | ((kv >> 2) & 1));
            int hd0 = m4 * 4;
            Vst[(hd0 + 0) * LDV + vcol] = __uint_as_float(f2tf32(vx.x));
            Vst[(hd0 + 1) * LDV + vcol] = __uint_as_float(f2tf32(vx.y));
            Vst[(hd0 + 2) * LDV + vcol] = __uint_as_float(f2tf32(vx.z));
            Vst[(hd0 + 3) * LDV + vcol] = __uint_as_float(f2tf32(vx.w));
        }
        for (int i = tid; i < AQ * 4; i += 256)
            Ms[i] = g_mask[((size_t)b * Ss + qt * AQ + (i >> 2)) * SW + kt * 4 + (i & 3)];
        __syncthreads();

        float sc[16][4];
#pragma unroll
        for (int t = 0; t < 16; t++)
#pragma unroll
            for (int j = 0; j < 4; j++) sc[t][j] = 0.f;
#pragma unroll
        for (int s = 0; s < 12; s++) {
#pragma unroll
            for (int t = 0; t < 16; t++) {
                uint2 bb = *(const uint2*)&Ks[(t * 8 + g) * LDK + s * 8 + 2 * tg];
                mma_tf32(sc[t], qa[s][0], qa[s][1], qa[s][2], qa[s][3], bb.x, bb.y);
            }
        }

        uint32_t mw0[4], mw1[4];
#pragma unroll
        for (int w = 0; w < 4; w++) {
            mw0[w] = Ms[row0 * 4 + w];
            mw1[w] = Ms[row1 * 4 + w];
        }
#pragma unroll
        for (int t = 0; t < 16; t++) {
            int bit0 = 8 * (t & 3) + 2 * tg;
            uint32_t w0 = mw0[t >> 2], w1 = mw1[t >> 2];
            float p0 = 0.f, p1 = 0.f, p2 = 0.f, p3 = 0.f;
            if ((w0 >> bit0) & 1u)       p0 = __expf(sc[t][0]);
            if ((w0 >> (bit0 + 1)) & 1u) p1 = __expf(sc[t][1]);
            if ((w1 >> bit0) & 1u)       p2 = __expf(sc[t][2]);
            if ((w1 >> (bit0 + 1)) & 1u) p3 = __expf(sc[t][3]);
            p0 = __uint_as_float(f2tf32(p0));
            p1 = __uint_as_float(f2tf32(p1));
            p2 = __uint_as_float(f2tf32(p2));
            p3 = __uint_as_float(f2tf32(p3));
            l0 += p0 + p1;
            l1 += p2 + p3;
            int cb = t * 8;
            Ps[row0 * LDP + cb + pos0] = p0;
            Ps[row0 * LDP + cb + pos1] = p1;
            Ps[row1 * LDP + cb + pos0] = p2;
            Ps[row1 * LDP + cb + pos1] = p3;
        }
        __syncwarp();

#pragma unroll
        for (int s = 0; s < 16; s++) {
            uint2 a02 = *(const uint2*)&Ps[row0 * LDP + s * 8 + 2 * tg];
            uint2 a13 = *(const uint2*)&Ps[row1 * LDP + s * 8 + 2 * tg];
#pragma unroll
            for (int t = 0; t < 12; t++) {
                uint2 bb = *(const uint2*)&Vst[(t * 8 + g) * LDV + s * 8 + 2 * tg];
                mma_tf32(acc[t], a02.x, a13.x, a02.y, a13.y, bb.x, bb.y);
            }
        }
    }

    l0 += __shfl_xor_sync(0xffffffffu, l0, 1);
    l0 += __shfl_xor_sync(0xffffffffu, l0, 2);
    l1 += __shfl_xor_sync(0xffffffffu, l1, 1);
    l1 += __shfl_xor_sync(0xffffffffu, l1, 2);
    float il0 = 1.f / l0, il1 = 1.f / l1;

    int q0 = qt * AQ + row0;
    size_t base0 = ((size_t)b * Ss + q0) * Dd + h * HD;
    size_t base1 = base0 + (size_t)8 * Dd;
#pragma unroll
    for (int t = 0; t < 12; t++) {
        int c = t * 8 + 2 * tg;
        float2 f0 = *(const float2*)&feat[base0 + c];
        float2 o0 = {acc[t][0] * il0 + f0.x, acc[t][1] * il0 + f0.y};
        *(float2*)&g_CTX[base0 + c] = o0;
        float2 f1 = *(const float2*)&feat[base1 + c];
        float2 o1 = {acc[t][2] * il1 + f1.x, acc[t][3] * il1 + f1.y};
        *(float2*)&g_CTX[base1 + c] = o1;
    }
}

// ---------------- 4) LayerNorm over D=768 ----------------
__global__ __launch_bounds__(256) void ln_kernel(
    const float* __restrict__ gamma, const float* __restrict__ beta,
    float* __restrict__ out)
{
    __shared__ float red[16];
    const int row = blockIdx.x;
    const int tid = threadIdx.x;
    const float* x = g_CTX + (size_t)row * Dd;

    float v[3];
    float sum = 0.f, sq = 0.f;
#pragma unroll
    for (int t = 0; t < 3; t++) {
        v[t] = x[tid + t * 256];
        sum += v[t];
        sq  = fmaf(v[t], v[t], sq);
    }
#pragma unroll
    for (int o = 16; o > 0; o >>= 1) {
        sum += __shfl_xor_sync(0xffffffffu, sum, o);
        sq  += __shfl_xor_sync(0xffffffffu, sq, o);
    }
    int warp = tid >> 5;
    if ((tid & 31) == 0) { red[warp] = sum; red[warp + 8] = sq; }
    __syncthreads();
    if (tid < 32) {
        float s = (tid < 8) ? red[tid] : 0.f;
        float q = (tid < 8) ? red[tid + 8] : 0.f;
#pragma unroll
        for (int o = 4; o > 0; o >>= 1) {
            s += __shfl_xor_sync(0xffffffffu, s, o);
            q += __shfl_xor_sync(0xffffffffu, q, o);
        }
        if (tid == 0) { red[0] = s; red[1] = q; }
    }
    __syncthreads();
    float mu = red[0] * (1.f / Dd);
    float var = red[1] * (1.f / Dd) - mu * mu;
    float rs = rsqrtf(var + 1e-5f);
#pragma unroll
    for (int t = 0; t < 3; t++) {
        int d = tid + t * 256;
        out[(size_t)row * Dd + d] = (v[t] - mu) * rs * gamma[d] + beta[d];
    }
}

// ---------------- launch ----------------
extern "C" void kernel_launch(void* const* d_in, const int* in_sizes, int n_in,
                              void* d_out, int out_size)
{
    const float* feat  = (const float*)d_in[0];
    const int*   adj   = (const int*)d_in[1];
    const float* Wq    = (const float*)d_in[2];
    const float* bq    = (const float*)d_in[3];
    const float* Wk    = (const float*)d_in[4];
    const float* bk    = (const float*)d_in[5];
    const float* Wv    = (const float*)d_in[6];
    const float* bv    = (const float*)d_in[7];
    const float* gamma = (const float*)d_in[8];
    const float* beta  = (const float*)d_in[9];
    float* out = (float*)d_out;

    // 1) pack adjacency into bitmask
    {
        size_t n = (size_t)Bb * Ss * Ss;
        pack_mask_kernel<<<(unsigned)(n / 256), 256>>>(adj);
    }

    // 2) QKV projections (tf32 tensor cores; single launch, z selects Q/K/V)
    dim3 pgrid(Dd / 128, M_ROWS / 128, 3);
    proj_kernel<<<pgrid, 256>>>(feat, Wq, bq, Wk, bk, Wv, bv);

    // 3) attention (tf32 tensor cores; >48KB dynamic smem)
    cudaFuncSetAttribute(attn_kernel, cudaFuncAttributeMaxDynamicSharedMemorySize,
                         ATTN_SMEM_BYTES);
    attn_kernel<<<dim3(Ss / AQ, Hh, Bb), 256, ATTN_SMEM_BYTES>>>(feat);

    // 4) layernorm
    ln_kernel<<<M_ROWS, 256>>>(gamma, beta, out);
}

// round 15
// speedup vs baseline: 3.8498x; 1.4699x over previous
#include <cuda_runtime.h>
#include <math.h>
#include <stdint.h>

#define Bb 8
#define Ss 2048
#define Dd 768
#define Hh 8
#define HD 96
#define M_ROWS (Bb*Ss)          // 16384
#define SW (Ss/32)              // mask words per row = 64

// ---------------- scratch (static device globals; no allocs) ----------------
// Q/K stored bf16, fragment-ready: [B,H,S,48 words], k-pair interleaved per 8-word chunk.
// V stored bf16 TRANSPOSED: [B,H,HD,S/2 words], kv-pair interleaved per 8-word chunk.
__device__ uint32_t g_Qbf[(size_t)Bb*Hh*Ss*48];
__device__ uint32_t g_Kbf[(size_t)Bb*Hh*Ss*48];
__device__ uint32_t g_Vbf[(size_t)Bb*Hh*HD*(Ss/2)];
__device__ float    g_CTX[(size_t)Bb*Ss*Dd];
__device__ uint32_t g_mask[(size_t)Bb*Ss*SW];

// interleave within 8-word chunks: word w and w+4 become adjacent
__device__ __forceinline__ int ilv8(int w) {
    return (w & ~7) | (((w & 3) << 1) | ((w >> 2) & 1));
}

__device__ __forceinline__ uint32_t packbf2(float hi, float lo) {
    uint32_t r;
    asm("cvt.rn.bf16x2.f32 %0, %1, %2;" : "=r"(r) : "f"(hi), "f"(lo));
    return r;
}

__device__ __forceinline__ void mma_bf16(float* c,
    uint32_t a0, uint32_t a1, uint32_t a2, uint32_t a3,
    uint32_t b0, uint32_t b1)
{
    asm volatile(
        "mma.sync.aligned.m16n8k16.row.col.f32.bf16.bf16.f32 "
        "{%0,%1,%2,%3}, {%4,%5,%6,%7}, {%8,%9}, {%0,%1,%2,%3};"
        : "+f"(c[0]), "+f"(c[1]), "+f"(c[2]), "+f"(c[3])
        : "r"(a0), "r"(a1), "r"(a2), "r"(a3), "r"(b0), "r"(b1));
}

// ---------------- 1) pack adj (int32 0/1) into bitmask ----------------
__global__ void pack_mask_kernel(const int* __restrict__ adj) {
    size_t idx = (size_t)blockIdx.x * blockDim.x + threadIdx.x;
    int v = adj[idx];
    unsigned bits = __ballot_sync(0xffffffffu, v != 0);
    if ((threadIdx.x & 31) == 0) g_mask[idx >> 5] = bits;
}

// ---------------- 2) merged QKV projection: bf16 mma, 128x128x32 tiles ----------------
#define PJW 24    // smem row stride in u32 words

__global__ __launch_bounds__(256, 2) void proj_kernel(
    const float* __restrict__ X,
    const float* __restrict__ Wq, const float* __restrict__ bq,
    const float* __restrict__ Wk, const float* __restrict__ bk,
    const float* __restrict__ Wv, const float* __restrict__ bv)
{
    const int z = blockIdx.z;
    const float* W    = (z == 0) ? Wq : (z == 1) ? Wk : Wv;
    const float* bias = (z == 0) ? bq : (z == 1) ? bk : bv;

    __shared__ uint32_t Xs[128 * PJW];
    __shared__ uint32_t Ws[128 * PJW];

    const int tid  = threadIdx.x;
    const int wid  = tid >> 5;
    const int lane = tid & 31;
    const int g    = lane >> 2;
    const int tg   = lane & 3;

    const int rowBase = blockIdx.y * 128;
    const int colBase = blockIdx.x * 128;

    const int mbase  = (wid >> 1) * 32;
    const int nwbase = (wid & 1) * 64;
    const int row0 = mbase + g;

    float sc0[8][4], sc1[8][4];
#pragma unroll
    for (int t = 0; t < 8; t++)
#pragma unroll
        for (int j = 0; j < 4; j++) { sc0[t][j] = 0.f; sc1[t][j] = 0.f; }

    const int jj = tid & 7;              // float4 index within row
    const int posA = ilv8(2 * jj);
    const int posB = ilv8(2 * jj + 1);

    float4 xr[4], wr[4];
#pragma unroll
    for (int i = 0; i < 4; i++) {
        int row = (tid >> 3) + i * 32;
        xr[i] = *(const float4*)&X[(size_t)(rowBase + row) * Dd + jj * 4];
        wr[i] = *(const float4*)&W[(size_t)(colBase + row) * Dd + jj * 4];
    }
#pragma unroll
    for (int i = 0; i < 4; i++) {
        int row = (tid >> 3) + i * 32;
        Xs[row * PJW + posA] = packbf2(xr[i].y, xr[i].x);
        Xs[row * PJW + posB] = packbf2(xr[i].w, xr[i].z);
        Ws[row * PJW + posA] = packbf2(wr[i].y, wr[i].x);
        Ws[row * PJW + posB] = packbf2(wr[i].w, wr[i].z);
    }
    __syncthreads();

    const int NCHUNK = Dd / 32;   // 24
    for (int c = 0; c < NCHUNK; c++) {
        const bool has_next = (c + 1 < NCHUNK);
        if (has_next) {
            int k0 = (c + 1) * 32;
#pragma unroll
            for (int i = 0; i < 4; i++) {
                int row = (tid >> 3) + i * 32;
                xr[i] = *(const float4*)&X[(size_t)(rowBase + row) * Dd + k0 + jj * 4];
                wr[i] = *(const float4*)&W[(size_t)(colBase + row) * Dd + k0 + jj * 4];
            }
        }
#pragma unroll
        for (int s = 0; s < 2; s++) {
            uint2 xa0 = *(const uint2*)&Xs[(row0 +  0) * PJW + s * 8 + 2 * tg];
            uint2 xa1 = *(const uint2*)&Xs[(row0 +  8) * PJW + s * 8 + 2 * tg];
            uint2 xa2 = *(const uint2*)&Xs[(row0 + 16) * PJW + s * 8 + 2 * tg];
            uint2 xa3 = *(const uint2*)&Xs[(row0 + 24) * PJW + s * 8 + 2 * tg];
#pragma unroll
            for (int t = 0; t < 8; t++) {
                uint2 bb = *(const uint2*)&Ws[(nwbase + t * 8 + g) * PJW + s * 8 + 2 * tg];
                mma_bf16(sc0[t], xa0.x, xa1.x, xa0.y, xa1.y, bb.x, bb.y);
                mma_bf16(sc1[t], xa2.x, xa3.x, xa2.y, xa3.y, bb.x, bb.y);
            }
        }
        if (has_next) {
            __syncthreads();
#pragma unroll
            for (int i = 0; i < 4; i++) {
                int row = (tid >> 3) + i * 32;
                Xs[row * PJW + posA] = packbf2(xr[i].y, xr[i].x);
                Xs[row * PJW + posB] = packbf2(xr[i].w, xr[i].z);
                Ws[row * PJW + posA] = packbf2(wr[i].y, wr[i].x);
                Ws[row * PJW + posB] = packbf2(wr[i].w, wr[i].z);
            }
            __syncthreads();
        }
    }

    // ---- epilogue: bias (+scale for Q), convert bf16, write fragment-ready layouts ----
    const float qscale = 0.10206207261596577f;   // 1/sqrt(96)
#pragma unroll
    for (int t = 0; t < 8; t++) {
        int n0 = colBase + nwbase + t * 8 + 2 * tg;       // even
        int h_ = n0 / HD, hd = n0 - h_ * HD;
        float bx = bias[n0], by = bias[n0 + 1];
#pragma unroll
        for (int mt = 0; mt < 4; mt++) {
            int m = rowBase + row0 + mt * 8;
            int b_ = m >> 11, s_ = m & (Ss - 1);
            const float* a = (mt < 2) ? sc0[t] : sc1[t];
            int o = (mt & 1) * 2;
            float vx = a[o] + bx, vy = a[o + 1] + by;
            if (z == 0) {
                vx *= qscale; vy *= qscale;
                int pos = ilv8(hd >> 1);
                g_Qbf[((size_t)(b_ * Hh + h_) * Ss + s_) * 48 + pos] = packbf2(vy, vx);
            } else if (z == 1) {
                int pos = ilv8(hd >> 1);
                g_Kbf[((size_t)(b_ * Hh + h_) * Ss + s_) * 48 + pos] = packbf2(vy, vx);
            } else {
                // V transposed: word (hd, kv-pair). Even-g lanes hold kv even; partner lane^4 holds kv+1.
                float px = __shfl_xor_sync(0xffffffffu, vx, 4);
                float py = __shfl_xor_sync(0xffffffffu, vy, 4);
                if ((g & 1) == 0) {
                    // BUGFIX (R12): kv word index must be PER-BATCH s_, not global m.
                    int pos = ilv8(s_ >> 1);   // s_ even here
                    size_t base = (size_t)(b_ * Hh + h_) * HD * (Ss / 2);
                    g_Vbf[base + (size_t)hd * (Ss / 2) + pos]       = packbf2(px, vx);
                    g_Vbf[base + (size_t)(hd + 1) * (Ss / 2) + pos] = packbf2(py, vy);
                }
            }
        }
    }
}

// ---------------- 3) flash attention v5: bf16 m16n8k16, pure-copy loads ----------------
#define AQ 128
#define AKV 128
#define LDK 56      // Ks  [kv][48w + pad]
#define LDV 72      // Vst [hd][64w + pad]
#define LDP 72      // Ps  [q][64w + pad]
#define ANKT (Ss / AKV)   // 16

#define ATTN_WORDS (AKV * LDK + HD * LDV + AQ * LDP + AQ * 4)
#define ATTN_SMEM_BYTES (ATTN_WORDS * 4)

__global__ __launch_bounds__(256, 1) void attn_kernel(const float* __restrict__ feat)
{
    extern __shared__ uint32_t smu[];
    uint32_t* Ks  = smu;                 // [128][56]
    uint32_t* Vst = Ks + AKV * LDK;      // [96][72]
    uint32_t* Ps  = Vst + HD * LDV;      // [128][72]
    uint32_t* Ms  = Ps + AQ * LDP;       // [128][4]

    const int tid  = threadIdx.x;
    const int wid  = tid >> 5;
    const int lane = tid & 31;
    const int g    = lane >> 2;
    const int tg   = lane & 3;
    const int qt = blockIdx.x, h = blockIdx.y, b = blockIdx.z;
    const int qbase = wid * 16;

    const int row0 = qbase + g;
    const int row1 = row0 + 8;

    const uint32_t* Qg = g_Qbf + ((size_t)(b * Hh + h) * Ss + qt * AQ) * 48;
    const uint32_t* Kg = g_Kbf + (size_t)(b * Hh + h) * Ss * 48;
    const uint32_t* Vg = g_Vbf + (size_t)(b * Hh + h) * HD * (Ss / 2);

    // Q fragments straight from global (pre-scaled, pre-interleaved)
    uint32_t qa[6][4];
#pragma unroll
    for (int s = 0; s < 6; s++) {
        uint2 r0 = *(const uint2*)&Qg[row0 * 48 + s * 8 + 2 * tg];
        uint2 r8 = *(const uint2*)&Qg[row1 * 48 + s * 8 + 2 * tg];
        qa[s][0] = r0.x; qa[s][1] = r8.x; qa[s][2] = r0.y; qa[s][3] = r8.y;
    }

    float acc[12][4];
#pragma unroll
    for (int t = 0; t < 12; t++)
#pragma unroll
        for (int j = 0; j < 4; j++) acc[t][j] = 0.f;

    float l0 = 0.f, l1 = 0.f;

    for (int kt = 0; kt < ANKT; kt++) {
        __syncthreads();

        // ---- pure-copy K/V tiles (no conversion) ----
        const uint4* Ksrc = (const uint4*)(Kg + (size_t)kt * AKV * 48);
        for (int i = tid; i < AKV * 12; i += 256) {
            int kv = i / 12, j = i - kv * 12;
            *(uint4*)&Ks[kv * LDK + j * 4] = Ksrc[i];
        }
        const uint4* Vsrc = (const uint4*)Vg;
        for (int i = tid; i < HD * 16; i += 256) {
            int hd = i >> 4, j = i & 15;
            *(uint4*)&Vst[hd * LDV + j * 4] = Vsrc[hd * (Ss / 8) + kt * 16 + j];
        }
        for (int i = tid; i < AQ * 4; i += 256)
            Ms[i] = g_mask[((size_t)b * Ss + qt * AQ + (i >> 2)) * SW + kt * 4 + (i & 3)];
        __syncthreads();

        // ---- QK^T: 6 k16-chunks x 16 kv-tiles ----
        float sc[16][4];
#pragma unroll
        for (int t = 0; t < 16; t++)
#pragma unroll
            for (int j = 0; j < 4; j++) sc[t][j] = 0.f;
#pragma unroll
        for (int s = 0; s < 6; s++) {
#pragma unroll
            for (int t = 0; t < 16; t++) {
                uint2 bb = *(const uint2*)&Ks[(t * 8 + g) * LDK + s * 8 + 2 * tg];
                mma_bf16(sc[t], qa[s][0], qa[s][1], qa[s][2], qa[s][3], bb.x, bb.y);
            }
        }

        // ---- mask + exp (no max), pack bf16, write P to warp-private rows ----
        uint32_t mw0[4], mw1[4];
#pragma unroll
        for (int w = 0; w < 4; w++) {
            mw0[w] = Ms[row0 * 4 + w];
            mw1[w] = Ms[row1 * 4 + w];
        }
#pragma unroll
        for (int t = 0; t < 16; t++) {
            int bit0 = 8 * (t & 3) + 2 * tg;
            uint32_t w0 = mw0[t >> 2], w1 = mw1[t >> 2];
            float p0 = 0.f, p1 = 0.f, p2 = 0.f, p3 = 0.f;
            if ((w0 >> bit0) & 1u)       p0 = __expf(sc[t][0]);
            if ((w0 >> (bit0 + 1)) & 1u) p1 = __expf(sc[t][1]);
            if ((w1 >> bit0) & 1u)       p2 = __expf(sc[t][2]);
            if ((w1 >> (bit0 + 1)) & 1u) p3 = __expf(sc[t][3]);
            l0 += p0 + p1;
            l1 += p2 + p3;
            int off = (t >> 1) * 8 + 2 * tg + (t & 1);
            Ps[row0 * LDP + off] = packbf2(p1, p0);
            Ps[row1 * LDP + off] = packbf2(p3, p2);
        }
        __syncwarp();

        // ---- PV: 8 kv16-chunks x 12 hd-tiles ----
#pragma unroll
        for (int s = 0; s < 8; s++) {
            uint2 a0 = *(const uint2*)&Ps[row0 * LDP + s * 8 + 2 * tg];
            uint2 a1 = *(const uint2*)&Ps[row1 * LDP + s * 8 + 2 * tg];
#pragma unroll
            for (int t = 0; t < 12; t++) {
                uint2 bb = *(const uint2*)&Vst[(t * 8 + g) * LDV + s * 8 + 2 * tg];
                mma_bf16(acc[t], a0.x, a1.x, a0.y, a1.y, bb.x, bb.y);
            }
        }
    }

    // ---- finalize: quad-reduce l, normalize, fuse residual ----
    l0 += __shfl_xor_sync(0xffffffffu, l0, 1);
    l0 += __shfl_xor_sync(0xffffffffu, l0, 2);
    l1 += __shfl_xor_sync(0xffffffffu, l1, 1);
    l1 += __shfl_xor_sync(0xffffffffu, l1, 2);
    float il0 = 1.f / l0, il1 = 1.f / l1;

    int q0 = qt * AQ + row0;
    size_t base0 = ((size_t)b * Ss + q0) * Dd + h * HD;
    size_t base1 = base0 + (size_t)8 * Dd;
#pragma unroll
    for (int t = 0; t < 12; t++) {
        int c = t * 8 + 2 * tg;
        float2 f0 = *(const float2*)&feat[base0 + c];
        float2 o0 = {acc[t][0] * il0 + f0.x, acc[t][1] * il0 + f0.y};
        *(float2*)&g_CTX[base0 + c] = o0;
        float2 f1 = *(const float2*)&feat[base1 + c];
        float2 o1 = {acc[t][2] * il1 + f1.x, acc[t][3] * il1 + f1.y};
        *(float2*)&g_CTX[base1 + c] = o1;
    }
}

// ---------------- 4) LayerNorm over D=768 ----------------
__global__ __launch_bounds__(256) void ln_kernel(
    const float* __restrict__ gamma, const float* __restrict__ beta,
    float* __restrict__ out)
{
    __shared__ float red[16];
    const int row = blockIdx.x;
    const int tid = threadIdx.x;
    const float* x = g_CTX + (size_t)row * Dd;

    float v[3];
    float sum = 0.f, sq = 0.f;
#pragma unroll
    for (int t = 0; t < 3; t++) {
        v[t] = x[tid + t * 256];
        sum += v[t];
        sq  = fmaf(v[t], v[t], sq);
    }
#pragma unroll
    for (int o = 16; o > 0; o >>= 1) {
        sum += __shfl_xor_sync(0xffffffffu, sum, o);
        sq  += __shfl_xor_sync(0xffffffffu, sq, o);
    }
    int warp = tid >> 5;
    if ((tid & 31) == 0) { red[warp] = sum; red[warp + 8] = sq; }
    __syncthreads();
    if (tid < 32) {
        float s = (tid < 8) ? red[tid] : 0.f;
        float q = (tid < 8) ? red[tid + 8] : 0.f;
#pragma unroll
        for (int o = 4; o > 0; o >>= 1) {
            s += __shfl_xor_sync(0xffffffffu, s, o);
            q += __shfl_xor_sync(0xffffffffu, q, o);
        }
        if (tid == 0) { red[0] = s; red[1] = q; }
    }
    __syncthreads();
    float mu = red[0] * (1.f / Dd);
    float var = red[1] * (1.f / Dd) - mu * mu;
    float rs = rsqrtf(var + 1e-5f);
#pragma unroll
    for (int t = 0; t < 3; t++) {
        int d = tid + t * 256;
        out[(size_t)row * Dd + d] = (v[t] - mu) * rs * gamma[d] + beta[d];
    }
}

// ---------------- launch ----------------
extern "C" void kernel_launch(void* const* d_in, const int* in_sizes, int n_in,
                              void* d_out, int out_size)
{
    const float* feat  = (const float*)d_in[0];
    const int*   adj   = (const int*)d_in[1];
    const float* Wq    = (const float*)d_in[2];
    const float* bq    = (const float*)d_in[3];
    const float* Wk    = (const float*)d_in[4];
    const float* bk    = (const float*)d_in[5];
    const float* Wv    = (const float*)d_in[6];
    const float* bv    = (const float*)d_in[7];
    const float* gamma = (const float*)d_in[8];
    const float* beta  = (const float*)d_in[9];
    float* out = (float*)d_out;

    // 1) pack adjacency into bitmask
    {
        size_t n = (size_t)Bb * Ss * Ss;
        pack_mask_kernel<<<(unsigned)(n / 256), 256>>>(adj);
    }

    // 2) QKV projections (bf16 tensor cores; writes fragment-ready layouts)
    dim3 pgrid(Dd / 128, M_ROWS / 128, 3);
    proj_kernel<<<pgrid, 256>>>(feat, Wq, bq, Wk, bk, Wv, bv);

    // 3) attention (bf16 tensor cores)
    cudaFuncSetAttribute(attn_kernel, cudaFuncAttributeMaxDynamicSharedMemorySize,
                         ATTN_SMEM_BYTES);
    attn_kernel<<<dim3(Ss / AQ, Hh, Bb), 256, ATTN_SMEM_BYTES>>>(feat);

    // 4) layernorm
    ln_kernel<<<M_ROWS, 256>>>(gamma, beta, out);
}